// round 6
// baseline (speedup 1.0000x reference)
#include <cuda_runtime.h>
#include <cuda_bf16.h>

#define BATCH 8
#define CIN   256
#define DQK   32
#define NPIX  4096   // 64*64
#define QTILE 128
#define KTILE 64

// Scratch (static device memory: allocation-free rule)
__device__ float g_qh[(size_t)BATCH * NPIX * DQK];  // tf32 hi part of q
__device__ float g_ql[(size_t)BATCH * NPIX * DQK];  // tf32 lo part of q
__device__ float g_v [(size_t)BATCH * NPIX * CIN];  // tf32-rounded v
__device__ float g_m [(size_t)BATCH * NPIX];        // |q_i|
__device__ float g_bm[BATCH];                       // max_j |q_j|

// ---------------------------------------------------------------------------
// helpers
// ---------------------------------------------------------------------------
__device__ __forceinline__ unsigned f2tf(float v) {
    unsigned r; asm("cvt.rna.tf32.f32 %0, %1;" : "=r"(r) : "f"(v)); return r;
}
__device__ __forceinline__ void mma8(float d[4], const unsigned a[4],
                                     unsigned b0, unsigned b1) {
    asm volatile(
        "mma.sync.aligned.m16n8k8.row.col.f32.tf32.tf32.f32 "
        "{%0,%1,%2,%3}, {%4,%5,%6,%7}, {%8,%9}, {%0,%1,%2,%3};"
        : "+f"(d[0]), "+f"(d[1]), "+f"(d[2]), "+f"(d[3])
        : "r"(a[0]), "r"(a[1]), "r"(a[2]), "r"(a[3]), "r"(b0), "r"(b1));
}

// ---------------------------------------------------------------------------
// Kernel 1: fused projection (same GEMM core as before; epilogue writes
// hi/lo tf32 split for q and tf32-rounded v).
// ---------------------------------------------------------------------------
__global__ __launch_bounds__(256) void proj_kernel(
    const float* __restrict__ x,
    const float* __restrict__ qw, const float* __restrict__ qb,
    const float* __restrict__ vw, const float* __restrict__ vb)
{
    int b  = blockIdx.z;
    int j0 = blockIdx.x * 64;
    int o0 = blockIdx.y * 64;

    __shared__ float Xs[32][64];
    __shared__ float Ws[32][65];

    int tid = threadIdx.x;
    int tx = tid & 15;
    int ty = tid >> 4;

    float acc[4][4] = {};
    const float* xb = x + (size_t)b * CIN * NPIX;

    for (int c0 = 0; c0 < CIN; c0 += 32) {
        #pragma unroll
        for (int r = 0; r < 8; r++) {
            int idx = tid + r * 256;
            int kk = idx >> 6, jj = idx & 63;
            Xs[kk][jj] = xb[(size_t)(c0 + kk) * NPIX + j0 + jj];
        }
        #pragma unroll
        for (int r = 0; r < 8; r++) {
            int idx = tid + r * 256;
            int oo = idx >> 5, kk = idx & 31;
            int o = o0 + oo;
            float w = 0.f;
            if (o < DQK)            w = qw[o * CIN + c0 + kk];
            else if (o < DQK + CIN) w = vw[(o - DQK) * CIN + c0 + kk];
            Ws[kk][oo] = w;
        }
        __syncthreads();
        #pragma unroll
        for (int kk = 0; kk < 32; kk++) {
            float a[4], w[4];
            #pragma unroll
            for (int i = 0; i < 4; i++) a[i] = Xs[kk][ty * 4 + i];
            #pragma unroll
            for (int i = 0; i < 4; i++) w[i] = Ws[kk][tx * 4 + i];
            #pragma unroll
            for (int i = 0; i < 4; i++)
                #pragma unroll
                for (int o = 0; o < 4; o++)
                    acc[i][o] += a[i] * w[o];
        }
        __syncthreads();
    }

    #pragma unroll
    for (int i = 0; i < 4; i++) {
        int j = j0 + ty * 4 + i;
        #pragma unroll
        for (int oi = 0; oi < 4; oi++) {
            int o = o0 + tx * 4 + oi;
            if (o < DQK) {
                float v = acc[i][oi] + qb[o];
                unsigned h = f2tf(v);
                unsigned l = f2tf(v - __uint_as_float(h));
                g_qh[((size_t)b * NPIX + j) * DQK + o] = __uint_as_float(h);
                g_ql[((size_t)b * NPIX + j) * DQK + o] = __uint_as_float(l);
            } else if (o < DQK + CIN) {
                float v = acc[i][oi] + vb[o - DQK];
                g_v[((size_t)b * NPIX + j) * CIN + (o - DQK)] =
                    __uint_as_float(f2tf(v));
            }
        }
    }
}

// ---------------------------------------------------------------------------
// Kernel 2: per-query norms + per-batch max norm (Cauchy-Schwarz bound).
// ---------------------------------------------------------------------------
__global__ __launch_bounds__(256) void qnorm_kernel()
{
    int b = blockIdx.x;
    __shared__ float red[256];
    int tid = threadIdx.x;
    float mx = 0.f;
    for (int i = tid; i < NPIX; i += 256) {
        const float* qh = g_qh + ((size_t)b * NPIX + i) * DQK;
        const float* ql = g_ql + ((size_t)b * NPIX + i) * DQK;
        float s = 0.f;
        #pragma unroll
        for (int d = 0; d < DQK; d++) {
            float v = qh[d] + ql[d];
            s += v * v;
        }
        float n = sqrtf(s);
        g_m[(size_t)b * NPIX + i] = n;
        mx = fmaxf(mx, n);
    }
    red[tid] = mx;
    __syncthreads();
    for (int s = 128; s > 0; s >>= 1) {
        if (tid < s) red[tid] = fmaxf(red[tid], red[tid + s]);
        __syncthreads();
    }
    if (tid == 0) g_bm[b] = red[0];
}

// ---------------------------------------------------------------------------
// Kernel 3: tensor-core flash attention, v2.
// S-phase: warp w computes S for queries w*16..+16 x all 64 keys (3-mma split).
// PV-phase: warp w -> queries (w>>2)*64..+64 x channels (w&3)*64..+64,
//           paired-row V (LDS.64 -> b0,b1), 4 A-frags reuse each B-load.
// Smem layout (bytes):
//   Khp 0..10240, Klp 10240..20480, Vp 20480..87040,
//   Ps 87040..121856, lbuf 121856..122368.  Epilogue Ot aliases [0..33792).
// ---------------------------------------------------------------------------
#define SM_KHP 0
#define SM_KLP 10240
#define SM_VP  20480
#define SM_PS  87040
#define SM_LB  121856
#define ATTN_SMEM 122368
#define VP_PITCH 260   // float2 per (kc,t) row
#define KP_PITCH 20    // float2 per key

__global__ __launch_bounds__(256, 1) void attn_tc_kernel(
    const float* __restrict__ x,
    const float* __restrict__ gamma,
    float* __restrict__ out)
{
    extern __shared__ char sm_raw[];
    float2* Khp = (float2*)(sm_raw + SM_KHP);
    float2* Klp = (float2*)(sm_raw + SM_KLP);
    float2* Vp  = (float2*)(sm_raw + SM_VP);
    float (*Ps)[68] = (float(*)[68])(sm_raw + SM_PS);
    float* lbuf = (float*)(sm_raw + SM_LB);
    float (*Ot)[132] = (float(*)[132])(sm_raw);   // epilogue alias

    int b   = blockIdx.y;
    int i0  = blockIdx.x * QTILE;
    int tid = threadIdx.x;
    int w    = tid >> 5;
    int lane = tid & 31;
    int g = lane >> 2;      // groupID
    int t = lane & 3;       // threadID_in_group
    int q0 = w * 16;        // S-phase query base
    int qg = w >> 2;        // PV query group (0/1)
    int cq = w & 3;         // PV channel group (0..3)

    const float* gqh = g_qh + (size_t)b * NPIX * DQK;
    const float* gql = g_ql + (size_t)b * NPIX * DQK;

    // softmax upper bounds for this thread's S-phase rows
    float Mb = g_bm[b];
    float m0 = g_m[(size_t)b * NPIX + i0 + q0 + g] * Mb;
    float m1 = g_m[(size_t)b * NPIX + i0 + q0 + g + 8] * Mb;

    // persistent Q fragments (already hi/lo split in gmem)
    unsigned qh[4][4], ql[4][4];
    {
        int r0 = i0 + q0 + g, r1 = r0 + 8;
        #pragma unroll
        for (int kc = 0; kc < 4; kc++) {
            int c0 = kc * 8 + t, c1 = c0 + 4;
            qh[kc][0] = __float_as_uint(gqh[(size_t)r0 * DQK + c0]);
            qh[kc][1] = __float_as_uint(gqh[(size_t)r1 * DQK + c0]);
            qh[kc][2] = __float_as_uint(gqh[(size_t)r0 * DQK + c1]);
            qh[kc][3] = __float_as_uint(gqh[(size_t)r1 * DQK + c1]);
            ql[kc][0] = __float_as_uint(gql[(size_t)r0 * DQK + c0]);
            ql[kc][1] = __float_as_uint(gql[(size_t)r1 * DQK + c0]);
            ql[kc][2] = __float_as_uint(gql[(size_t)r0 * DQK + c1]);
            ql[kc][3] = __float_as_uint(gql[(size_t)r1 * DQK + c1]);
        }
    }

    // per-thread swizzled channel offsets for Vp reads
    int gl = g & 3, ghi = g >> 2;
    int ntoff[8];
    #pragma unroll
    for (int nt = 0; nt < 8; nt++)
        ntoff[nt] = nt * 8 + ((gl + (nt >> 1)) & 3);
    int cbase = cq * 64 + 4 * ghi;

    float acc[4][8][4];
    #pragma unroll
    for (int f = 0; f < 4; f++)
        #pragma unroll
        for (int nt = 0; nt < 8; nt++)
            #pragma unroll
            for (int k = 0; k < 4; k++) acc[f][nt][k] = 0.f;
    float l0 = 0.f, l1 = 0.f;

    const float4* vbase = (const float4*)(g_v + (size_t)b * NPIX * CIN);

    for (int j0 = 0; j0 < NPIX; j0 += KTILE) {
        __syncthreads();

        // --- load K tile into paired layout: Khp[key][kc*4+t] = (d, d+4) ---
        #pragma unroll
        for (int r = 0; r < 4; r++) {
            int idx = tid + r * 256;            // 0..1023
            int key = idx >> 4, p = idx & 15;
            int d0 = (p >> 2) * 8 + (p & 3);
            const float* kh = gqh + (size_t)(j0 + key) * DQK;
            const float* kl = gql + (size_t)(j0 + key) * DQK;
            Khp[key * KP_PITCH + p] = make_float2(kh[d0], kh[d0 + 4]);
            Klp[key * KP_PITCH + p] = make_float2(kl[d0], kl[d0 + 4]);
        }
        // --- load V tile into paired rows with intra-float4 swizzle ---
        #pragma unroll
        for (int r = 0; r < 8; r++) {
            int idx = tid + r * 256;            // 0..2047
            int row = idx >> 6, c4 = idx & 63;  // row = kc*4 + t
            int keyA = j0 + (row >> 2) * 8 + (row & 3);
            float4 va = vbase[(size_t)keyA * 64 + c4];
            float4 vb2 = vbase[(size_t)(keyA + 4) * 64 + c4];
            int sbase = row * VP_PITCH + c4 * 4;
            int sw = (c4 >> 2) & 3;
            Vp[sbase + ((0 + sw) & 3)] = make_float2(va.x, vb2.x);
            Vp[sbase + ((1 + sw) & 3)] = make_float2(va.y, vb2.y);
            Vp[sbase + ((2 + sw) & 3)] = make_float2(va.z, vb2.z);
            Vp[sbase + ((3 + sw) & 3)] = make_float2(va.w, vb2.w);
        }
        __syncthreads();

        // --- S = Q K^T (split tf32), P = exp(S-m) -> Ps ---
        #pragma unroll
        for (int nt = 0; nt < 8; nt++) {
            float d[4] = {0.f, 0.f, 0.f, 0.f};
            #pragma unroll
            for (int kc = 0; kc < 4; kc++) {
                float2 bh = Khp[(nt * 8 + g) * KP_PITCH + kc * 4 + t];
                float2 bl = Klp[(nt * 8 + g) * KP_PITCH + kc * 4 + t];
                unsigned bh0 = __float_as_uint(bh.x), bh1 = __float_as_uint(bh.y);
                mma8(d, qh[kc], bh0, bh1);
                mma8(d, qh[kc], __float_as_uint(bl.x), __float_as_uint(bl.y));
                mma8(d, ql[kc], bh0, bh1);
            }
            float p0 = __uint_as_float(f2tf(__expf(d[0] - m0)));
            float p1 = __uint_as_float(f2tf(__expf(d[1] - m0)));
            float p2 = __uint_as_float(f2tf(__expf(d[2] - m1)));
            float p3 = __uint_as_float(f2tf(__expf(d[3] - m1)));
            l0 += p0 + p1;
            l1 += p2 + p3;
            *(float2*)&Ps[q0 + g][nt * 8 + 2 * t]     = make_float2(p0, p1);
            *(float2*)&Ps[q0 + g + 8][nt * 8 + 2 * t] = make_float2(p2, p3);
        }
        __syncthreads();

        // --- O += P V : M=64 (4 A-frags) per B-load ---
        #pragma unroll
        for (int kc = 0; kc < 8; kc++) {
            unsigned a[4][4];
            #pragma unroll
            for (int f = 0; f < 4; f++) {
                int rq = qg * 64 + f * 16 + g;
                a[f][0] = __float_as_uint(Ps[rq][kc * 8 + t]);
                a[f][1] = __float_as_uint(Ps[rq + 8][kc * 8 + t]);
                a[f][2] = __float_as_uint(Ps[rq][kc * 8 + t + 4]);
                a[f][3] = __float_as_uint(Ps[rq + 8][kc * 8 + t + 4]);
            }
            int rowoff = (kc * 4 + t) * VP_PITCH + cbase;
            #pragma unroll
            for (int nt = 0; nt < 8; nt++) {
                float2 bv = Vp[rowoff + ntoff[nt]];
                unsigned b0 = __float_as_uint(bv.x);
                unsigned b1 = __float_as_uint(bv.y);
                #pragma unroll
                for (int f = 0; f < 4; f++) mma8(acc[f][nt], a[f], b0, b1);
            }
        }
    }

    // --- l reduction: quad lanes hold column-partials of each row ---
    l0 += __shfl_xor_sync(0xffffffffu, l0, 1);
    l0 += __shfl_xor_sync(0xffffffffu, l0, 2);
    l1 += __shfl_xor_sync(0xffffffffu, l1, 1);
    l1 += __shfl_xor_sync(0xffffffffu, l1, 2);
    if (t == 0) {
        lbuf[q0 + g]     = 1.f / l0;
        lbuf[q0 + g + 8] = 1.f / l1;
    }
    __syncthreads();

    float inv[4][2];
    #pragma unroll
    for (int f = 0; f < 4; f++) {
        inv[f][0] = lbuf[qg * 64 + f * 16 + g];
        inv[f][1] = lbuf[qg * 64 + f * 16 + g + 8];
    }
    float gam = gamma[0];

    // --- epilogue: 4 chunks of 64 channels; owning warps transpose to Ot,
    //     then all warps do fused gamma*o + x stores ---
    #pragma unroll
    for (int cc = 0; cc < 4; cc++) {
        __syncthreads();
        if (cq == cc) {
            #pragma unroll
            for (int f = 0; f < 4; f++) {
                int rq = qg * 64 + f * 16 + g;
                #pragma unroll
                for (int nt = 0; nt < 8; nt++) {
                    int cl = nt * 8 + 2 * t;
                    Ot[cl][rq]         = acc[f][nt][0] * inv[f][0];
                    Ot[cl + 1][rq]     = acc[f][nt][1] * inv[f][0];
                    Ot[cl][rq + 8]     = acc[f][nt][2] * inv[f][1];
                    Ot[cl + 1][rq + 8] = acc[f][nt][3] * inv[f][1];
                }
            }
        }
        __syncthreads();
        #pragma unroll
        for (int r = 0; r < 8; r++) {
            int idx = tid + r * 256;
            int cl = idx >> 5, q4 = idx & 31;
            int c = cc * 64 + cl;
            size_t base = ((size_t)b * CIN + c) * NPIX + i0 + q4 * 4;
            float4 o = *(float4*)&Ot[cl][q4 * 4];
            float4 xv = *(const float4*)(x + base);
            float4 rv;
            rv.x = gam * o.x + xv.x;
            rv.y = gam * o.y + xv.y;
            rv.z = gam * o.z + xv.z;
            rv.w = gam * o.w + xv.w;
            *(float4*)(out + base) = rv;
        }
    }
}

// ---------------------------------------------------------------------------
extern "C" void kernel_launch(void* const* d_in, const int* in_sizes, int n_in,
                              void* d_out, int out_size)
{
    const float* x     = (const float*)d_in[0];
    const float* q_w   = (const float*)d_in[1];
    const float* q_b   = (const float*)d_in[2];
    const float* v_w   = (const float*)d_in[3];
    const float* v_b   = (const float*)d_in[4];
    const float* gamma = (const float*)d_in[5];
    float* out = (float*)d_out;

    cudaFuncSetAttribute(attn_tc_kernel,
                         cudaFuncAttributeMaxDynamicSharedMemorySize, ATTN_SMEM);

    proj_kernel<<<dim3(NPIX / 64, 5, BATCH), 256>>>(x, q_w, q_b, v_w, v_b);
    qnorm_kernel<<<BATCH, 256>>>();
    attn_tc_kernel<<<dim3(NPIX / QTILE, BATCH), 256, ATTN_SMEM>>>(x, gamma, out);
}

// round 7
// speedup vs baseline: 1.1170x; 1.1170x over previous
#include <cuda_runtime.h>
#include <cuda_bf16.h>

#define BATCH 8
#define CIN   256
#define DQK   32
#define NPIX  4096   // 64*64
#define QTILE 128
#define KTILE 64

// Scratch (static device memory: allocation-free rule)
__device__ float g_q[(size_t)BATCH * NPIX * DQK];   // [b][i][d]
__device__ float g_v[(size_t)BATCH * NPIX * CIN];   // [b][j][c]
__device__ float g_m[(size_t)BATCH * NPIX];         // |q_i|
__device__ float g_bm[BATCH];                       // max_j |q_j|

// ---------------------------------------------------------------------------
// helpers
// ---------------------------------------------------------------------------
__device__ __forceinline__ unsigned f2tf(float v) {
    unsigned r; asm("cvt.rna.tf32.f32 %0, %1;" : "=r"(r) : "f"(v)); return r;
}
__device__ __forceinline__ void mma8(float d[4], const unsigned a[4],
                                     unsigned b0, unsigned b1) {
    asm volatile(
        "mma.sync.aligned.m16n8k8.row.col.f32.tf32.tf32.f32 "
        "{%0,%1,%2,%3}, {%4,%5,%6,%7}, {%8,%9}, {%0,%1,%2,%3};"
        : "+f"(d[0]), "+f"(d[1]), "+f"(d[2]), "+f"(d[3])
        : "r"(a[0]), "r"(a[1]), "r"(a[2]), "r"(a[3]), "r"(b0), "r"(b1));
}

// ---------------------------------------------------------------------------
// Kernel 1: fused projection (unchanged from the 1049us version).
// ---------------------------------------------------------------------------
__global__ __launch_bounds__(256) void proj_kernel(
    const float* __restrict__ x,
    const float* __restrict__ qw, const float* __restrict__ qb,
    const float* __restrict__ vw, const float* __restrict__ vb)
{
    int b  = blockIdx.z;
    int j0 = blockIdx.x * 64;
    int o0 = blockIdx.y * 64;

    __shared__ float Xs[32][64];
    __shared__ float Ws[32][65];

    int tid = threadIdx.x;
    int tx = tid & 15;
    int ty = tid >> 4;

    float acc[4][4] = {};
    const float* xb = x + (size_t)b * CIN * NPIX;

    for (int c0 = 0; c0 < CIN; c0 += 32) {
        #pragma unroll
        for (int r = 0; r < 8; r++) {
            int idx = tid + r * 256;
            int kk = idx >> 6, jj = idx & 63;
            Xs[kk][jj] = xb[(size_t)(c0 + kk) * NPIX + j0 + jj];
        }
        #pragma unroll
        for (int r = 0; r < 8; r++) {
            int idx = tid + r * 256;
            int oo = idx >> 5, kk = idx & 31;
            int o = o0 + oo;
            float w = 0.f;
            if (o < DQK)            w = qw[o * CIN + c0 + kk];
            else if (o < DQK + CIN) w = vw[(o - DQK) * CIN + c0 + kk];
            Ws[kk][oo] = w;
        }
        __syncthreads();
        #pragma unroll
        for (int kk = 0; kk < 32; kk++) {
            float a[4], w[4];
            #pragma unroll
            for (int i = 0; i < 4; i++) a[i] = Xs[kk][ty * 4 + i];
            #pragma unroll
            for (int i = 0; i < 4; i++) w[i] = Ws[kk][tx * 4 + i];
            #pragma unroll
            for (int i = 0; i < 4; i++)
                #pragma unroll
                for (int o = 0; o < 4; o++)
                    acc[i][o] += a[i] * w[o];
        }
        __syncthreads();
    }

    #pragma unroll
    for (int i = 0; i < 4; i++) {
        int j = j0 + ty * 4 + i;
        #pragma unroll
        for (int oi = 0; oi < 4; oi++) {
            int o = o0 + tx * 4 + oi;
            if (o < DQK)
                g_q[((size_t)b * NPIX + j) * DQK + o] = acc[i][oi] + qb[o];
            else if (o < DQK + CIN)
                g_v[((size_t)b * NPIX + j) * CIN + (o - DQK)] = acc[i][oi] + vb[o - DQK];
        }
    }
}

// ---------------------------------------------------------------------------
// Kernel 2: per-query norms + per-batch max norm (Cauchy-Schwarz bound).
// ---------------------------------------------------------------------------
__global__ __launch_bounds__(256) void qnorm_kernel()
{
    int b = blockIdx.x;
    __shared__ float red[256];
    int tid = threadIdx.x;
    float mx = 0.f;
    for (int i = tid; i < NPIX; i += 256) {
        const float* q = g_q + ((size_t)b * NPIX + i) * DQK;
        float s = 0.f;
        #pragma unroll
        for (int d = 0; d < DQK; d++) s += q[d] * q[d];
        float n = sqrtf(s);
        g_m[(size_t)b * NPIX + i] = n;
        mx = fmaxf(mx, n);
    }
    red[tid] = mx;
    __syncthreads();
    for (int s = 128; s > 0; s >>= 1) {
        if (tid < s) red[tid] = fmaxf(red[tid], red[tid + s]);
        __syncthreads();
    }
    if (tid == 0) g_bm[b] = red[0];
}

// ---------------------------------------------------------------------------
// Kernel 3: tensor-core flash attention (R5 base, PV remapped to 32q x 128c
// per warp: 2 A-frags reuse every B-load -> PV smem B traffic halved).
// S-phase: warp w -> queries w*16..+16 x all 64 keys (3-mma split tf32).
// PV-phase: warp w -> queries (w>>1)*32..+32 x channels (w&1)*128..+128.
// ---------------------------------------------------------------------------
__global__ __launch_bounds__(256, 1) void attn_tc_kernel(
    const float* __restrict__ x,
    const float* __restrict__ gamma,
    float* __restrict__ out)
{
    extern __shared__ char sm_raw[];
    float (*Kh)[36]  = (float(*)[36])(sm_raw);                 //  9216 B
    float (*Kl)[36]  = (float(*)[36])(sm_raw + 9216);          //  9216 B
    float (*Vs)[264] = (float(*)[264])(sm_raw + 18432);        // 67584 B
    float (*Ps)[68]  = (float(*)[68])(sm_raw + 86016);         // 34816 B
    float* lbuf      = (float*)(sm_raw + 120832);              //   512 B  (tot 121344)
    float (*Ot)[132] = (float(*)[132])(sm_raw);                // epilogue alias

    int b   = blockIdx.y;
    int i0  = blockIdx.x * QTILE;
    int tid = threadIdx.x;
    int w    = tid >> 5;
    int lane = tid & 31;
    int g = lane >> 2;      // groupID
    int t = lane & 3;       // threadID_in_group
    int q0 = w * 16;        // S-phase query base
    int qg = w >> 1;        // PV query group (0..3): 32 queries
    int cg = w & 1;         // PV channel group (0..1): 128 channels

    const float* gq_b = g_q + (size_t)b * NPIX * DQK;

    // softmax upper bounds for this thread's S-phase rows
    float Mb = g_bm[b];
    float m0 = g_m[(size_t)b * NPIX + i0 + q0 + g] * Mb;
    float m1 = g_m[(size_t)b * NPIX + i0 + q0 + g + 8] * Mb;

    // Q fragments (hi/lo split), persistent: A[kc] covers dims kc*8..kc*8+7
    unsigned qh[4][4], ql[4][4];
    #pragma unroll
    for (int kc = 0; kc < 4; kc++) {
        int r0 = i0 + q0 + g, r1 = r0 + 8;
        int c0 = kc * 8 + t,  c1 = c0 + 4;
        float v00 = gq_b[(size_t)r0 * DQK + c0];
        float v10 = gq_b[(size_t)r1 * DQK + c0];
        float v01 = gq_b[(size_t)r0 * DQK + c1];
        float v11 = gq_b[(size_t)r1 * DQK + c1];
        qh[kc][0] = f2tf(v00); ql[kc][0] = f2tf(v00 - __uint_as_float(qh[kc][0]));
        qh[kc][1] = f2tf(v10); ql[kc][1] = f2tf(v10 - __uint_as_float(qh[kc][1]));
        qh[kc][2] = f2tf(v01); ql[kc][2] = f2tf(v01 - __uint_as_float(qh[kc][2]));
        qh[kc][3] = f2tf(v11); ql[kc][3] = f2tf(v11 - __uint_as_float(qh[kc][3]));
    }

    float acc[2][16][4];
    #pragma unroll
    for (int f = 0; f < 2; f++)
        #pragma unroll
        for (int nt = 0; nt < 16; nt++)
            #pragma unroll
            for (int k = 0; k < 4; k++) acc[f][nt][k] = 0.f;
    float l0 = 0.f, l1 = 0.f;

    const float4* vbase = (const float4*)(g_v + (size_t)b * NPIX * CIN);

    for (int j0 = 0; j0 < NPIX; j0 += KTILE) {
        __syncthreads();   // protect Vs/Kh/Ps from previous readers

        // --- load K tile (64x32) with hi/lo tf32 split ---
        #pragma unroll
        for (int r = 0; r < 8; r++) {
            int idx = tid + r * 256;
            int key = idx >> 5, d = idx & 31;
            float v = gq_b[(size_t)(j0 + key) * DQK + d];
            unsigned h = f2tf(v);
            Kh[key][d] = __uint_as_float(h);
            Kl[key][d] = __uint_as_float(f2tf(v - __uint_as_float(h)));
        }
        // --- load V tile (64x256) as tf32 ---
        #pragma unroll
        for (int r = 0; r < 16; r++) {
            int idx = tid + r * 256;        // float4 index over 64*64
            int key = idx >> 6, c4 = idx & 63;
            float4 v = vbase[(size_t)j0 * 64 + idx];
            float4 o;
            o.x = __uint_as_float(f2tf(v.x));
            o.y = __uint_as_float(f2tf(v.y));
            o.z = __uint_as_float(f2tf(v.z));
            o.w = __uint_as_float(f2tf(v.w));
            *(float4*)&Vs[key][c4 * 4] = o;
        }
        __syncthreads();

        // --- S = Q K^T (split tf32), P = exp(S-m), store to Ps ---
        #pragma unroll
        for (int nt = 0; nt < 8; nt++) {
            float d[4] = {0.f, 0.f, 0.f, 0.f};
            #pragma unroll
            for (int kc = 0; kc < 4; kc++) {
                unsigned bh0 = __float_as_uint(Kh[nt * 8 + g][kc * 8 + t]);
                unsigned bh1 = __float_as_uint(Kh[nt * 8 + g][kc * 8 + t + 4]);
                unsigned bl0 = __float_as_uint(Kl[nt * 8 + g][kc * 8 + t]);
                unsigned bl1 = __float_as_uint(Kl[nt * 8 + g][kc * 8 + t + 4]);
                mma8(d, qh[kc], bh0, bh1);
                mma8(d, qh[kc], bl0, bl1);
                mma8(d, ql[kc], bh0, bh1);
            }
            float p0 = __uint_as_float(f2tf(__expf(d[0] - m0)));
            float p1 = __uint_as_float(f2tf(__expf(d[1] - m0)));
            float p2 = __uint_as_float(f2tf(__expf(d[2] - m1)));
            float p3 = __uint_as_float(f2tf(__expf(d[3] - m1)));
            l0 += p0 + p1;
            l1 += p2 + p3;
            *(float2*)&Ps[q0 + g][nt * 8 + 2 * t]     = make_float2(p0, p1);
            *(float2*)&Ps[q0 + g + 8][nt * 8 + 2 * t] = make_float2(p2, p3);
        }
        __syncthreads();

        // --- O += P V : 32q x 128c per warp, 2 A-frags per B-load ---
        #pragma unroll
        for (int kc = 0; kc < 8; kc++) {
            unsigned a[2][4];
            #pragma unroll
            for (int f = 0; f < 2; f++) {
                int rq = qg * 32 + f * 16 + g;
                a[f][0] = __float_as_uint(Ps[rq][kc * 8 + t]);
                a[f][1] = __float_as_uint(Ps[rq + 8][kc * 8 + t]);
                a[f][2] = __float_as_uint(Ps[rq][kc * 8 + t + 4]);
                a[f][3] = __float_as_uint(Ps[rq + 8][kc * 8 + t + 4]);
            }
            #pragma unroll
            for (int nt = 0; nt < 16; nt++) {
                unsigned b0 = __float_as_uint(Vs[kc * 8 + t][cg * 128 + nt * 8 + g]);
                unsigned b1 = __float_as_uint(Vs[kc * 8 + t + 4][cg * 128 + nt * 8 + g]);
                mma8(acc[0][nt], a[0], b0, b1);
                mma8(acc[1][nt], a[1], b0, b1);
            }
        }
    }

    // --- l reduction: quad lanes hold column-partials of each row ---
    l0 += __shfl_xor_sync(0xffffffffu, l0, 1);
    l0 += __shfl_xor_sync(0xffffffffu, l0, 2);
    l1 += __shfl_xor_sync(0xffffffffu, l1, 1);
    l1 += __shfl_xor_sync(0xffffffffu, l1, 2);
    if (t == 0) {
        lbuf[q0 + g]     = 1.f / l0;
        lbuf[q0 + g + 8] = 1.f / l1;
    }
    __syncthreads();

    float inv[2][2];
    #pragma unroll
    for (int f = 0; f < 2; f++) {
        inv[f][0] = lbuf[qg * 32 + f * 16 + g];
        inv[f][1] = lbuf[qg * 32 + f * 16 + g + 8];
    }
    float gam = gamma[0];

    // --- epilogue: 4 chunks of 64 channels; owning warps transpose to Ot,
    //     then all warps do fused gamma*o + x stores ---
    #pragma unroll
    for (int cc = 0; cc < 4; cc++) {
        __syncthreads();
        if (cg == (cc >> 1)) {
            int ntbase = (cc & 1) * 8;
            #pragma unroll
            for (int f = 0; f < 2; f++) {
                int rq = qg * 32 + f * 16 + g;
                #pragma unroll
                for (int ntl = 0; ntl < 8; ntl++) {
                    int nt = ntbase + ntl;
                    int cl = ntl * 8 + 2 * t;
                    Ot[cl][rq]         = acc[f][nt][0] * inv[f][0];
                    Ot[cl + 1][rq]     = acc[f][nt][1] * inv[f][0];
                    Ot[cl][rq + 8]     = acc[f][nt][2] * inv[f][1];
                    Ot[cl + 1][rq + 8] = acc[f][nt][3] * inv[f][1];
                }
            }
        }
        __syncthreads();
        #pragma unroll
        for (int r = 0; r < 8; r++) {
            int idx = tid + r * 256;
            int cl = idx >> 5, q4 = idx & 31;
            int c = cc * 64 + cl;
            size_t base = ((size_t)b * CIN + c) * NPIX + i0 + q4 * 4;
            float4 o = *(float4*)&Ot[cl][q4 * 4];
            float4 xv = *(const float4*)(x + base);
            float4 rv;
            rv.x = gam * o.x + xv.x;
            rv.y = gam * o.y + xv.y;
            rv.z = gam * o.z + xv.z;
            rv.w = gam * o.w + xv.w;
            *(float4*)(out + base) = rv;
        }
    }
}

// ---------------------------------------------------------------------------
extern "C" void kernel_launch(void* const* d_in, const int* in_sizes, int n_in,
                              void* d_out, int out_size)
{
    const float* x     = (const float*)d_in[0];
    const float* q_w   = (const float*)d_in[1];
    const float* q_b   = (const float*)d_in[2];
    const float* v_w   = (const float*)d_in[3];
    const float* v_b   = (const float*)d_in[4];
    const float* gamma = (const float*)d_in[5];
    float* out = (float*)d_out;

    const int ATTN_SMEM = 121344;
    cudaFuncSetAttribute(attn_tc_kernel,
                         cudaFuncAttributeMaxDynamicSharedMemorySize, ATTN_SMEM);

    proj_kernel<<<dim3(NPIX / 64, 5, BATCH), 256>>>(x, q_w, q_b, v_w, v_b);
    qnorm_kernel<<<BATCH, 256>>>();
    attn_tc_kernel<<<dim3(NPIX / QTILE, BATCH), 256, ATTN_SMEM>>>(x, gamma, out);
}

// round 8
// speedup vs baseline: 1.2178x; 1.0902x over previous
#include <cuda_runtime.h>
#include <cuda_bf16.h>

#define BATCH 8
#define CIN   256
#define DQK   32
#define NPIX  4096   // 64*64
#define QTILE 128
#define KTILE 64

// Scratch (static device memory: allocation-free rule)
__device__ float g_q[(size_t)BATCH * NPIX * DQK];   // [b][i][d]  fp32
__device__ float g_v[(size_t)BATCH * NPIX * CIN];   // [b][j][c]  tf32-rounded
__device__ float g_m[(size_t)BATCH * NPIX];         // |q_i|
__device__ float g_bm[BATCH];                       // max_j |q_j|

// ---------------------------------------------------------------------------
// helpers
// ---------------------------------------------------------------------------
__device__ __forceinline__ unsigned f2tf(float v) {
    unsigned r; asm("cvt.rna.tf32.f32 %0, %1;" : "=r"(r) : "f"(v)); return r;
}
__device__ __forceinline__ void mma8(float d[4], const unsigned a[4],
                                     unsigned b0, unsigned b1) {
    asm volatile(
        "mma.sync.aligned.m16n8k8.row.col.f32.tf32.tf32.f32 "
        "{%0,%1,%2,%3}, {%4,%5,%6,%7}, {%8,%9}, {%0,%1,%2,%3};"
        : "+f"(d[0]), "+f"(d[1]), "+f"(d[2]), "+f"(d[3])
        : "r"(a[0]), "r"(a[1]), "r"(a[2]), "r"(a[3]), "r"(b0), "r"(b1));
}
__device__ __forceinline__ void cp16(float* smem_dst, const float* gmem_src) {
    unsigned s = (unsigned)__cvta_generic_to_shared(smem_dst);
    asm volatile("cp.async.cg.shared.global [%0], [%1], 16;" :: "r"(s), "l"(gmem_src));
}
#define CP_COMMIT() asm volatile("cp.async.commit_group;")
#define CP_WAIT0()  asm volatile("cp.async.wait_group 0;")

// ---------------------------------------------------------------------------
// Kernel 1: fused projection (v now tf32-rounded at write).
// ---------------------------------------------------------------------------
__global__ __launch_bounds__(256) void proj_kernel(
    const float* __restrict__ x,
    const float* __restrict__ qw, const float* __restrict__ qb,
    const float* __restrict__ vw, const float* __restrict__ vb)
{
    int b  = blockIdx.z;
    int j0 = blockIdx.x * 64;
    int o0 = blockIdx.y * 64;

    __shared__ float Xs[32][64];
    __shared__ float Ws[32][65];

    int tid = threadIdx.x;
    int tx = tid & 15;
    int ty = tid >> 4;

    float acc[4][4] = {};
    const float* xb = x + (size_t)b * CIN * NPIX;

    for (int c0 = 0; c0 < CIN; c0 += 32) {
        #pragma unroll
        for (int r = 0; r < 8; r++) {
            int idx = tid + r * 256;
            int kk = idx >> 6, jj = idx & 63;
            Xs[kk][jj] = xb[(size_t)(c0 + kk) * NPIX + j0 + jj];
        }
        #pragma unroll
        for (int r = 0; r < 8; r++) {
            int idx = tid + r * 256;
            int oo = idx >> 5, kk = idx & 31;
            int o = o0 + oo;
            float w = 0.f;
            if (o < DQK)            w = qw[o * CIN + c0 + kk];
            else if (o < DQK + CIN) w = vw[(o - DQK) * CIN + c0 + kk];
            Ws[kk][oo] = w;
        }
        __syncthreads();
        #pragma unroll
        for (int kk = 0; kk < 32; kk++) {
            float a[4], w[4];
            #pragma unroll
            for (int i = 0; i < 4; i++) a[i] = Xs[kk][ty * 4 + i];
            #pragma unroll
            for (int i = 0; i < 4; i++) w[i] = Ws[kk][tx * 4 + i];
            #pragma unroll
            for (int i = 0; i < 4; i++)
                #pragma unroll
                for (int o = 0; o < 4; o++)
                    acc[i][o] += a[i] * w[o];
        }
        __syncthreads();
    }

    #pragma unroll
    for (int i = 0; i < 4; i++) {
        int j = j0 + ty * 4 + i;
        #pragma unroll
        for (int oi = 0; oi < 4; oi++) {
            int o = o0 + tx * 4 + oi;
            if (o < DQK) {
                g_q[((size_t)b * NPIX + j) * DQK + o] = acc[i][oi] + qb[o];
            } else if (o < DQK + CIN) {
                float v = acc[i][oi] + vb[o - DQK];
                g_v[((size_t)b * NPIX + j) * CIN + (o - DQK)] =
                    __uint_as_float(f2tf(v));
            }
        }
    }
}

// ---------------------------------------------------------------------------
// Kernel 2: per-query norms + per-batch max norm (Cauchy-Schwarz bound).
// ---------------------------------------------------------------------------
__global__ __launch_bounds__(256) void qnorm_kernel()
{
    int b = blockIdx.x;
    __shared__ float red[256];
    int tid = threadIdx.x;
    float mx = 0.f;
    for (int i = tid; i < NPIX; i += 256) {
        const float* q = g_q + ((size_t)b * NPIX + i) * DQK;
        float s = 0.f;
        #pragma unroll
        for (int d = 0; d < DQK; d++) s += q[d] * q[d];
        float n = sqrtf(s);
        g_m[(size_t)b * NPIX + i] = n;
        mx = fmaxf(mx, n);
    }
    red[tid] = mx;
    __syncthreads();
    for (int s = 128; s > 0; s >>= 1) {
        if (tid < s) red[tid] = fmaxf(red[tid], red[tid + s]);
        __syncthreads();
    }
    if (tid == 0) g_bm[b] = red[0];
}

// ---------------------------------------------------------------------------
// Kernel 3: tensor-core flash attention, double-buffered cp.async pipeline.
// S-phase: warp w -> queries w*16..+16 x all 64 keys; K split hi/lo in regs.
// PV-phase: warp w -> queries (w>>1)*32..+32 x channels (w&1)*128..+128.
// Smem: Kf 2x9216 | Vs 2x67584 | Ps 34816 | lbuf 512  = 188928 B.
// ---------------------------------------------------------------------------
#define KP 36    // K pitch (floats)
#define VP 264   // V pitch (floats)
#define SM_K  0
#define SM_V  18432
#define SM_PS 153600
#define SM_LB 188416
#define ATTN_SMEM 188928

__global__ __launch_bounds__(256, 1) void attn_tc_kernel(
    const float* __restrict__ x,
    const float* __restrict__ gamma,
    float* __restrict__ out)
{
    extern __shared__ char sm_raw[];
    float* Kf = (float*)(sm_raw + SM_K);      // 2 buffers, stride 64*KP
    float* Vs = (float*)(sm_raw + SM_V);      // 2 buffers, stride 64*VP
    float (*Ps)[68] = (float(*)[68])(sm_raw + SM_PS);
    float* lbuf = (float*)(sm_raw + SM_LB);
    float (*Ot)[132] = (float(*)[132])(sm_raw);   // epilogue alias

    int b   = blockIdx.y;
    int i0  = blockIdx.x * QTILE;
    int tid = threadIdx.x;
    int w    = tid >> 5;
    int lane = tid & 31;
    int g = lane >> 2;      // groupID
    int t = lane & 3;       // threadID_in_group
    int q0 = w * 16;        // S-phase query base
    int qg = w >> 1;        // PV query group (0..3)
    int cg = w & 1;         // PV channel group (0..1)

    const float* gq_b = g_q + (size_t)b * NPIX * DQK;
    const float* gv_b = g_v + (size_t)b * NPIX * CIN;

    // softmax upper bounds
    float Mb = g_bm[b];
    float m0 = g_m[(size_t)b * NPIX + i0 + q0 + g] * Mb;
    float m1 = g_m[(size_t)b * NPIX + i0 + q0 + g + 8] * Mb;

    // persistent Q fragments (hi/lo tf32 split from fp32 gmem)
    unsigned qh[4][4], ql[4][4];
    #pragma unroll
    for (int kc = 0; kc < 4; kc++) {
        int r0 = i0 + q0 + g, r1 = r0 + 8;
        int c0 = kc * 8 + t,  c1 = c0 + 4;
        float v00 = gq_b[(size_t)r0 * DQK + c0];
        float v10 = gq_b[(size_t)r1 * DQK + c0];
        float v01 = gq_b[(size_t)r0 * DQK + c1];
        float v11 = gq_b[(size_t)r1 * DQK + c1];
        qh[kc][0] = f2tf(v00); ql[kc][0] = f2tf(v00 - __uint_as_float(qh[kc][0]));
        qh[kc][1] = f2tf(v10); ql[kc][1] = f2tf(v10 - __uint_as_float(qh[kc][1]));
        qh[kc][2] = f2tf(v01); ql[kc][2] = f2tf(v01 - __uint_as_float(qh[kc][2]));
        qh[kc][3] = f2tf(v11); ql[kc][3] = f2tf(v11 - __uint_as_float(qh[kc][3]));
    }

    float acc[2][16][4];
    #pragma unroll
    for (int f = 0; f < 2; f++)
        #pragma unroll
        for (int nt = 0; nt < 16; nt++)
            #pragma unroll
            for (int k = 0; k < 4; k++) acc[f][nt][k] = 0.f;
    float l0 = 0.f, l1 = 0.f;

    // ---- prefetch tile 0 into buffer 0 ----
    {
        float* Kb = Kf;
        float* Vb = Vs;
        #pragma unroll
        for (int r = 0; r < 2; r++) {
            int idx = tid + r * 256;
            int key = idx >> 3, c4 = idx & 7;
            cp16(Kb + key * KP + c4 * 4, gq_b + (size_t)key * DQK + c4 * 4);
        }
        #pragma unroll
        for (int r = 0; r < 16; r++) {
            int idx = tid + r * 256;
            int key = idx >> 6, c4 = idx & 63;
            cp16(Vb + key * VP + c4 * 4, gv_b + (size_t)key * CIN + c4 * 4);
        }
        CP_COMMIT();
    }

    for (int jt = 0; jt < NPIX / KTILE; jt++) {
        int buf = jt & 1;
        float* Kb = Kf + buf * (64 * KP);
        float* Vb = Vs + buf * (64 * VP);

        CP_WAIT0();          // buffer `buf` ready
        __syncthreads();     // all warps done with prev use of the other buffer

        // ---- prefetch tile jt+1 into the other buffer ----
        if (jt + 1 < NPIX / KTILE) {
            int jn = (jt + 1) * KTILE;
            float* Kn = Kf + (1 - buf) * (64 * KP);
            float* Vn = Vs + (1 - buf) * (64 * VP);
            #pragma unroll
            for (int r = 0; r < 2; r++) {
                int idx = tid + r * 256;
                int key = idx >> 3, c4 = idx & 7;
                cp16(Kn + key * KP + c4 * 4, gq_b + (size_t)(jn + key) * DQK + c4 * 4);
            }
            #pragma unroll
            for (int r = 0; r < 16; r++) {
                int idx = tid + r * 256;
                int key = idx >> 6, c4 = idx & 63;
                cp16(Vn + key * VP + c4 * 4, gv_b + (size_t)(jn + key) * CIN + c4 * 4);
            }
            CP_COMMIT();
        }

        // ---- S = Q K^T (split tf32 in regs), P = exp(S-m) -> Ps ----
        #pragma unroll
        for (int nt = 0; nt < 8; nt++) {
            float d[4] = {0.f, 0.f, 0.f, 0.f};
            const float* krow = Kb + (nt * 8 + g) * KP;
            #pragma unroll
            for (int kc = 0; kc < 4; kc++) {
                float k0 = krow[kc * 8 + t];
                float k1 = krow[kc * 8 + t + 4];
                unsigned h0 = f2tf(k0);
                unsigned h1 = f2tf(k1);
                unsigned l0u = f2tf(k0 - __uint_as_float(h0));
                unsigned l1u = f2tf(k1 - __uint_as_float(h1));
                mma8(d, qh[kc], h0, h1);
                mma8(d, qh[kc], l0u, l1u);
                mma8(d, ql[kc], h0, h1);
            }
            float p0 = __uint_as_float(f2tf(__expf(d[0] - m0)));
            float p1 = __uint_as_float(f2tf(__expf(d[1] - m0)));
            float p2 = __uint_as_float(f2tf(__expf(d[2] - m1)));
            float p3 = __uint_as_float(f2tf(__expf(d[3] - m1)));
            l0 += p0 + p1;
            l1 += p2 + p3;
            *(float2*)&Ps[q0 + g][nt * 8 + 2 * t]     = make_float2(p0, p1);
            *(float2*)&Ps[q0 + g + 8][nt * 8 + 2 * t] = make_float2(p2, p3);
        }
        __syncthreads();

        // ---- O += P V : 32q x 128c per warp ----
        #pragma unroll
        for (int kc = 0; kc < 8; kc++) {
            unsigned a[2][4];
            #pragma unroll
            for (int f = 0; f < 2; f++) {
                int rq = qg * 32 + f * 16 + g;
                a[f][0] = __float_as_uint(Ps[rq][kc * 8 + t]);
                a[f][1] = __float_as_uint(Ps[rq + 8][kc * 8 + t]);
                a[f][2] = __float_as_uint(Ps[rq][kc * 8 + t + 4]);
                a[f][3] = __float_as_uint(Ps[rq + 8][kc * 8 + t + 4]);
            }
            const float* vr0 = Vb + (kc * 8 + t) * VP + cg * 128;
            const float* vr1 = Vb + (kc * 8 + t + 4) * VP + cg * 128;
            #pragma unroll
            for (int nt = 0; nt < 16; nt++) {
                unsigned b0 = __float_as_uint(vr0[nt * 8 + g]);
                unsigned b1 = __float_as_uint(vr1[nt * 8 + g]);
                mma8(acc[0][nt], a[0], b0, b1);
                mma8(acc[1][nt], a[1], b0, b1);
            }
        }
    }

    // ---- l reduction ----
    l0 += __shfl_xor_sync(0xffffffffu, l0, 1);
    l0 += __shfl_xor_sync(0xffffffffu, l0, 2);
    l1 += __shfl_xor_sync(0xffffffffu, l1, 1);
    l1 += __shfl_xor_sync(0xffffffffu, l1, 2);
    if (t == 0) {
        lbuf[q0 + g]     = 1.f / l0;
        lbuf[q0 + g + 8] = 1.f / l1;
    }
    __syncthreads();

    float inv[2][2];
    #pragma unroll
    for (int f = 0; f < 2; f++) {
        inv[f][0] = lbuf[qg * 32 + f * 16 + g];
        inv[f][1] = lbuf[qg * 32 + f * 16 + g + 8];
    }
    float gam = gamma[0];

    // ---- epilogue: 4 chunks of 64 channels ----
    #pragma unroll
    for (int cc = 0; cc < 4; cc++) {
        __syncthreads();
        if (cg == (cc >> 1)) {
            int ntbase = (cc & 1) * 8;
            #pragma unroll
            for (int f = 0; f < 2; f++) {
                int rq = qg * 32 + f * 16 + g;
                #pragma unroll
                for (int ntl = 0; ntl < 8; ntl++) {
                    int nt = ntbase + ntl;
                    int cl = ntl * 8 + 2 * t;
                    Ot[cl][rq]         = acc[f][nt][0] * inv[f][0];
                    Ot[cl + 1][rq]     = acc[f][nt][1] * inv[f][0];
                    Ot[cl][rq + 8]     = acc[f][nt][2] * inv[f][1];
                    Ot[cl + 1][rq + 8] = acc[f][nt][3] * inv[f][1];
                }
            }
        }
        __syncthreads();
        #pragma unroll
        for (int r = 0; r < 8; r++) {
            int idx = tid + r * 256;
            int cl = idx >> 5, q4 = idx & 31;
            int c = cc * 64 + cl;
            size_t base = ((size_t)b * CIN + c) * NPIX + i0 + q4 * 4;
            float4 o = *(float4*)&Ot[cl][q4 * 4];
            float4 xv = *(const float4*)(x + base);
            float4 rv;
            rv.x = gam * o.x + xv.x;
            rv.y = gam * o.y + xv.y;
            rv.z = gam * o.z + xv.z;
            rv.w = gam * o.w + xv.w;
            *(float4*)(out + base) = rv;
        }
    }
}

// ---------------------------------------------------------------------------
extern "C" void kernel_launch(void* const* d_in, const int* in_sizes, int n_in,
                              void* d_out, int out_size)
{
    const float* x     = (const float*)d_in[0];
    const float* q_w   = (const float*)d_in[1];
    const float* q_b   = (const float*)d_in[2];
    const float* v_w   = (const float*)d_in[3];
    const float* v_b   = (const float*)d_in[4];
    const float* gamma = (const float*)d_in[5];
    float* out = (float*)d_out;

    cudaFuncSetAttribute(attn_tc_kernel,
                         cudaFuncAttributeMaxDynamicSharedMemorySize, ATTN_SMEM);

    proj_kernel<<<dim3(NPIX / 64, 5, BATCH), 256>>>(x, q_w, q_b, v_w, v_b);
    qnorm_kernel<<<BATCH, 256>>>();
    attn_tc_kernel<<<dim3(NPIX / QTILE, BATCH), 256, ATTN_SMEM>>>(x, gamma, out);
}

// round 9
// speedup vs baseline: 1.3351x; 1.0963x over previous
#include <cuda_runtime.h>
#include <cuda_bf16.h>

#define BATCH 8
#define CIN   256
#define DQK   32
#define NPIX  4096   // 64*64
#define NTILE (NPIX / 64)
#define QTILE 128
#define KTILE 64

// Scratch (static device memory: allocation-free rule)
__device__ float g_q  [(size_t)BATCH * NPIX * DQK];  // fp32 q (Q frags + norms)
__device__ float g_khp[(size_t)BATCH * NPIX * DQK];  // paired tf32-hi K: [key][p]=f2(d,d+4)
__device__ float g_klp[(size_t)BATCH * NPIX * DQK];  // paired tf32-lo K
__device__ float g_vp [(size_t)BATCH * NPIX * CIN];  // paired tf32 V: [tile][row][c]=f2(keyA,keyB)
__device__ float g_m  [(size_t)BATCH * NPIX];        // |q_i|
__device__ float g_bm [BATCH];                       // max_j |q_j|

// ---------------------------------------------------------------------------
// helpers
// ---------------------------------------------------------------------------
__device__ __forceinline__ unsigned f2tf(float v) {
    unsigned r; asm("cvt.rna.tf32.f32 %0, %1;" : "=r"(r) : "f"(v)); return r;
}
__device__ __forceinline__ void mma8(float d[4], const unsigned a[4],
                                     unsigned b0, unsigned b1) {
    asm volatile(
        "mma.sync.aligned.m16n8k8.row.col.f32.tf32.tf32.f32 "
        "{%0,%1,%2,%3}, {%4,%5,%6,%7}, {%8,%9}, {%0,%1,%2,%3};"
        : "+f"(d[0]), "+f"(d[1]), "+f"(d[2]), "+f"(d[3])
        : "r"(a[0]), "r"(a[1]), "r"(a[2]), "r"(a[3]), "r"(b0), "r"(b1));
}
__device__ __forceinline__ void mma8f(float d[4], const unsigned a[4],
                                      float b0, float b1) {
    mma8(d, a, __float_as_uint(b0), __float_as_uint(b1));
}
__device__ __forceinline__ void cp16(float* smem_dst, const float* gmem_src) {
    unsigned s = (unsigned)__cvta_generic_to_shared(smem_dst);
    asm volatile("cp.async.cg.shared.global [%0], [%1], 16;" :: "r"(s), "l"(gmem_src));
}
#define CP_COMMIT() asm volatile("cp.async.commit_group;")
#define CP_WAIT0()  asm volatile("cp.async.wait_group 0;")

// ---------------------------------------------------------------------------
// Kernel 1: fused projection. Epilogue writes:
//   q  -> g_q (fp32)  AND  g_khp/g_klp in paired-tf32 layout
//   v  -> g_vp in paired-row tf32 layout
// ---------------------------------------------------------------------------
__global__ __launch_bounds__(256) void proj_kernel(
    const float* __restrict__ x,
    const float* __restrict__ qw, const float* __restrict__ qb,
    const float* __restrict__ vw, const float* __restrict__ vb)
{
    int b  = blockIdx.z;
    int j0 = blockIdx.x * 64;
    int o0 = blockIdx.y * 64;

    __shared__ float Xs[32][64];
    __shared__ float Ws[32][65];

    int tid = threadIdx.x;
    int tx = tid & 15;
    int ty = tid >> 4;

    float acc[4][4] = {};
    const float* xb = x + (size_t)b * CIN * NPIX;

    for (int c0 = 0; c0 < CIN; c0 += 32) {
        #pragma unroll
        for (int r = 0; r < 8; r++) {
            int idx = tid + r * 256;
            int kk = idx >> 6, jj = idx & 63;
            Xs[kk][jj] = xb[(size_t)(c0 + kk) * NPIX + j0 + jj];
        }
        #pragma unroll
        for (int r = 0; r < 8; r++) {
            int idx = tid + r * 256;
            int oo = idx >> 5, kk = idx & 31;
            int o = o0 + oo;
            float w = 0.f;
            if (o < DQK)            w = qw[o * CIN + c0 + kk];
            else if (o < DQK + CIN) w = vw[(o - DQK) * CIN + c0 + kk];
            Ws[kk][oo] = w;
        }
        __syncthreads();
        #pragma unroll
        for (int kk = 0; kk < 32; kk++) {
            float a[4], w[4];
            #pragma unroll
            for (int i = 0; i < 4; i++) a[i] = Xs[kk][ty * 4 + i];
            #pragma unroll
            for (int i = 0; i < 4; i++) w[i] = Ws[kk][tx * 4 + i];
            #pragma unroll
            for (int i = 0; i < 4; i++)
                #pragma unroll
                for (int o = 0; o < 4; o++)
                    acc[i][o] += a[i] * w[o];
        }
        __syncthreads();
    }

    #pragma unroll
    for (int i = 0; i < 4; i++) {
        int j = j0 + ty * 4 + i;
        #pragma unroll
        for (int oi = 0; oi < 4; oi++) {
            int o = o0 + tx * 4 + oi;
            if (o < DQK) {
                float v = acc[i][oi] + qb[o];
                g_q[((size_t)b * NPIX + j) * DQK + o] = v;
                unsigned h = f2tf(v);
                unsigned l = f2tf(v - __uint_as_float(h));
                // paired layout: p = (d>>3)*4 + (d&3), slot = (d>>2)&1
                int d = o;
                int p = (d >> 3) * 4 + (d & 3);
                int slot = (d >> 2) & 1;
                size_t addr = (((size_t)b * NPIX + j) * 16 + p) * 2 + slot;
                g_khp[addr] = __uint_as_float(h);
                g_klp[addr] = __uint_as_float(l);
            } else if (o < DQK + CIN) {
                float v = acc[i][oi] + vb[o - DQK];
                int c = o - DQK;
                // paired-row layout within 64-key tile
                int jt = j >> 6;
                int k6 = j & 63;
                int tt = k6 & 7;
                int row = (k6 >> 3) * 4 + (tt & 3);
                int slot = tt >> 2;
                size_t addr = ((((size_t)b * NTILE + jt) * 32 + row) * 256 + c) * 2 + slot;
                g_vp[addr] = __uint_as_float(f2tf(v));
            }
        }
    }
}

// ---------------------------------------------------------------------------
// Kernel 2: per-query norms + per-batch max norm (Cauchy-Schwarz bound).
// ---------------------------------------------------------------------------
__global__ __launch_bounds__(256) void qnorm_kernel()
{
    int b = blockIdx.x;
    __shared__ float red[256];
    int tid = threadIdx.x;
    float mx = 0.f;
    for (int i = tid; i < NPIX; i += 256) {
        const float* q = g_q + ((size_t)b * NPIX + i) * DQK;
        float s = 0.f;
        #pragma unroll
        for (int d = 0; d < DQK; d++) s += q[d] * q[d];
        float n = sqrtf(s);
        g_m[(size_t)b * NPIX + i] = n;
        mx = fmaxf(mx, n);
    }
    red[tid] = mx;
    __syncthreads();
    for (int s = 128; s > 0; s >>= 1) {
        if (tid < s) red[tid] = fmaxf(red[tid], red[tid + s]);
        __syncthreads();
    }
    if (tid == 0) g_bm[b] = red[0];
}

// ---------------------------------------------------------------------------
// Kernel 3: tensor-core flash attention.
// cp.async double-buffered; K hi/lo and V pre-paired in gmem -> LDS.64 frags,
// zero cvt in the hot loop.
// Smem (bytes): Khp 2x10240 | Klp 2x10240 | Vp 2x66560 | Ps 34816 | lbuf 512
//             = 209408.
// ---------------------------------------------------------------------------
#define KPITCH 20    // float2 per key (16 used + 4 pad)
#define VPITCH 260   // float2 per paired row (256 used + 4 pad)
#define SM_KH  0
#define SM_KL  20480
#define SM_V   40960
#define SM_PS  174080
#define SM_LB  208896
#define ATTN_SMEM 209408

__global__ __launch_bounds__(256, 1) void attn_tc_kernel(
    const float* __restrict__ x,
    const float* __restrict__ gamma,
    float* __restrict__ out)
{
    extern __shared__ char sm_raw[];
    float* KhS = (float*)(sm_raw + SM_KH);   // 2 buffers, stride 64*KPITCH*2 floats
    float* KlS = (float*)(sm_raw + SM_KL);
    float* VpS = (float*)(sm_raw + SM_V);    // 2 buffers, stride 32*VPITCH*2 floats
    float (*Ps)[68] = (float(*)[68])(sm_raw + SM_PS);
    float* lbuf = (float*)(sm_raw + SM_LB);
    float (*Ot)[132] = (float(*)[132])(sm_raw);   // epilogue alias

    int b   = blockIdx.y;
    int i0  = blockIdx.x * QTILE;
    int tid = threadIdx.x;
    int w    = tid >> 5;
    int lane = tid & 31;
    int g = lane >> 2;      // groupID
    int t = lane & 3;       // threadID_in_group
    int q0 = w * 16;        // S-phase query base
    int qg = w >> 1;        // PV query group (0..3)
    int cg = w & 1;         // PV channel group (0..1)

    const float* gq_b  = g_q   + (size_t)b * NPIX * DQK;
    const float* gkh_b = g_khp + (size_t)b * NPIX * DQK;
    const float* gkl_b = g_klp + (size_t)b * NPIX * DQK;
    const float* gvp_b = g_vp  + (size_t)b * NPIX * CIN;

    // softmax upper bounds
    float Mb = g_bm[b];
    float m0 = g_m[(size_t)b * NPIX + i0 + q0 + g] * Mb;
    float m1 = g_m[(size_t)b * NPIX + i0 + q0 + g + 8] * Mb;

    // persistent Q fragments (hi/lo tf32 split from fp32 gmem, once)
    unsigned qh[4][4], ql[4][4];
    #pragma unroll
    for (int kc = 0; kc < 4; kc++) {
        int r0 = i0 + q0 + g, r1 = r0 + 8;
        int c0 = kc * 8 + t,  c1 = c0 + 4;
        float v00 = gq_b[(size_t)r0 * DQK + c0];
        float v10 = gq_b[(size_t)r1 * DQK + c0];
        float v01 = gq_b[(size_t)r0 * DQK + c1];
        float v11 = gq_b[(size_t)r1 * DQK + c1];
        qh[kc][0] = f2tf(v00); ql[kc][0] = f2tf(v00 - __uint_as_float(qh[kc][0]));
        qh[kc][1] = f2tf(v10); ql[kc][1] = f2tf(v10 - __uint_as_float(qh[kc][1]));
        qh[kc][2] = f2tf(v01); ql[kc][2] = f2tf(v01 - __uint_as_float(qh[kc][2]));
        qh[kc][3] = f2tf(v11); ql[kc][3] = f2tf(v11 - __uint_as_float(qh[kc][3]));
    }

    float acc[2][16][4];
    #pragma unroll
    for (int f = 0; f < 2; f++)
        #pragma unroll
        for (int nt = 0; nt < 16; nt++)
            #pragma unroll
            for (int k = 0; k < 4; k++) acc[f][nt][k] = 0.f;
    float l0 = 0.f, l1 = 0.f;

    // ---- prefetch tile 0 into buffer 0 ----
    {
        #pragma unroll
        for (int r = 0; r < 2; r++) {
            int ch = tid + r * 256;               // 512 x 16B chunks for K arrays
            int key = ch >> 3, c = ch & 7;
            cp16(KhS + key * (KPITCH * 2) + c * 4, gkh_b + (size_t)key * 32 + c * 4);
            cp16(KlS + key * (KPITCH * 2) + c * 4, gkl_b + (size_t)key * 32 + c * 4);
        }
        #pragma unroll
        for (int r = 0; r < 16; r++) {
            int ch = tid + r * 256;               // 4096 x 16B chunks for V
            int row = ch >> 7, c = ch & 127;
            cp16(VpS + row * (VPITCH * 2) + c * 4, gvp_b + (size_t)row * 512 + c * 4);
        }
        CP_COMMIT();
    }

    for (int jt = 0; jt < NTILE; jt++) {
        int buf = jt & 1;
        float* KhB = KhS + buf * (64 * KPITCH * 2);
        float* KlB = KlS + buf * (64 * KPITCH * 2);
        float* VpB = VpS + buf * (32 * VPITCH * 2);

        CP_WAIT0();
        __syncthreads();

        // ---- prefetch tile jt+1 into the other buffer ----
        if (jt + 1 < NTILE) {
            int jn = (jt + 1) * KTILE;
            float* KhN = KhS + (1 - buf) * (64 * KPITCH * 2);
            float* KlN = KlS + (1 - buf) * (64 * KPITCH * 2);
            float* VpN = VpS + (1 - buf) * (32 * VPITCH * 2);
            #pragma unroll
            for (int r = 0; r < 2; r++) {
                int ch = tid + r * 256;
                int key = ch >> 3, c = ch & 7;
                cp16(KhN + key * (KPITCH * 2) + c * 4,
                     gkh_b + (size_t)(jn + key) * 32 + c * 4);
                cp16(KlN + key * (KPITCH * 2) + c * 4,
                     gkl_b + (size_t)(jn + key) * 32 + c * 4);
            }
            #pragma unroll
            for (int r = 0; r < 16; r++) {
                int ch = tid + r * 256;
                int row = ch >> 7, c = ch & 127;
                cp16(VpN + row * (VPITCH * 2) + c * 4,
                     gvp_b + (size_t)(jt + 1) * 16384 + (size_t)row * 512 + c * 4);
            }
            CP_COMMIT();
        }

        // ---- S = Q K^T (3-mma split, frags via LDS.64), P = exp(S-m) ----
        #pragma unroll
        for (int nt = 0; nt < 8; nt++) {
            float d[4] = {0.f, 0.f, 0.f, 0.f};
            const float2* khrow = (const float2*)KhB + (nt * 8 + g) * KPITCH;
            const float2* klrow = (const float2*)KlB + (nt * 8 + g) * KPITCH;
            #pragma unroll
            for (int kc = 0; kc < 4; kc++) {
                float2 bh = khrow[kc * 4 + t];
                float2 bl = klrow[kc * 4 + t];
                mma8f(d, qh[kc], bh.x, bh.y);
                mma8f(d, qh[kc], bl.x, bl.y);
                mma8f(d, ql[kc], bh.x, bh.y);
            }
            float p0 = __expf(d[0] - m0);
            float p1 = __expf(d[1] - m0);
            float p2 = __expf(d[2] - m1);
            float p3 = __expf(d[3] - m1);
            l0 += p0 + p1;
            l1 += p2 + p3;
            *(float2*)&Ps[q0 + g][nt * 8 + 2 * t]     = make_float2(p0, p1);
            *(float2*)&Ps[q0 + g + 8][nt * 8 + 2 * t] = make_float2(p2, p3);
        }
        __syncthreads();

        // ---- O += P V : 32q x 128c per warp, B-frags via LDS.64 ----
        #pragma unroll
        for (int kc = 0; kc < 8; kc++) {
            unsigned a[2][4];
            #pragma unroll
            for (int f = 0; f < 2; f++) {
                int rq = qg * 32 + f * 16 + g;
                a[f][0] = __float_as_uint(Ps[rq][kc * 8 + t]);
                a[f][1] = __float_as_uint(Ps[rq + 8][kc * 8 + t]);
                a[f][2] = __float_as_uint(Ps[rq][kc * 8 + t + 4]);
                a[f][3] = __float_as_uint(Ps[rq + 8][kc * 8 + t + 4]);
            }
            const float2* vrow = (const float2*)VpB + (kc * 4 + t) * VPITCH + cg * 128;
            #pragma unroll
            for (int nt = 0; nt < 16; nt++) {
                float2 bv = vrow[nt * 8 + g];
                mma8f(acc[0][nt], a[0], bv.x, bv.y);
                mma8f(acc[1][nt], a[1], bv.x, bv.y);
            }
        }
    }

    // ---- l reduction ----
    l0 += __shfl_xor_sync(0xffffffffu, l0, 1);
    l0 += __shfl_xor_sync(0xffffffffu, l0, 2);
    l1 += __shfl_xor_sync(0xffffffffu, l1, 1);
    l1 += __shfl_xor_sync(0xffffffffu, l1, 2);
    if (t == 0) {
        lbuf[q0 + g]     = 1.f / l0;
        lbuf[q0 + g + 8] = 1.f / l1;
    }
    __syncthreads();

    float inv[2][2];
    #pragma unroll
    for (int f = 0; f < 2; f++) {
        inv[f][0] = lbuf[qg * 32 + f * 16 + g];
        inv[f][1] = lbuf[qg * 32 + f * 16 + g + 8];
    }
    float gam = gamma[0];

    // ---- epilogue: 4 chunks of 64 channels ----
    #pragma unroll
    for (int cc = 0; cc < 4; cc++) {
        __syncthreads();
        if (cg == (cc >> 1)) {
            int ntbase = (cc & 1) * 8;
            #pragma unroll
            for (int f = 0; f < 2; f++) {
                int rq = qg * 32 + f * 16 + g;
                #pragma unroll
                for (int ntl = 0; ntl < 8; ntl++) {
                    int nt = ntbase + ntl;
                    int cl = ntl * 8 + 2 * t;
                    Ot[cl][rq]         = acc[f][nt][0] * inv[f][0];
                    Ot[cl + 1][rq]     = acc[f][nt][1] * inv[f][0];
                    Ot[cl][rq + 8]     = acc[f][nt][2] * inv[f][1];
                    Ot[cl + 1][rq + 8] = acc[f][nt][3] * inv[f][1];
                }
            }
        }
        __syncthreads();
        #pragma unroll
        for (int r = 0; r < 8; r++) {
            int idx = tid + r * 256;
            int cl = idx >> 5, q4 = idx & 31;
            int c = cc * 64 + cl;
            size_t base = ((size_t)b * CIN + c) * NPIX + i0 + q4 * 4;
            float4 o = *(float4*)&Ot[cl][q4 * 4];
            float4 xv = *(const float4*)(x + base);
            float4 rv;
            rv.x = gam * o.x + xv.x;
            rv.y = gam * o.y + xv.y;
            rv.z = gam * o.z + xv.z;
            rv.w = gam * o.w + xv.w;
            *(float4*)(out + base) = rv;
        }
    }
}

// ---------------------------------------------------------------------------
extern "C" void kernel_launch(void* const* d_in, const int* in_sizes, int n_in,
                              void* d_out, int out_size)
{
    const float* x     = (const float*)d_in[0];
    const float* q_w   = (const float*)d_in[1];
    const float* q_b   = (const float*)d_in[2];
    const float* v_w   = (const float*)d_in[3];
    const float* v_b   = (const float*)d_in[4];
    const float* gamma = (const float*)d_in[5];
    float* out = (float*)d_out;

    cudaFuncSetAttribute(attn_tc_kernel,
                         cudaFuncAttributeMaxDynamicSharedMemorySize, ATTN_SMEM);

    proj_kernel<<<dim3(NPIX / 64, 5, BATCH), 256>>>(x, q_w, q_b, v_w, v_b);
    qnorm_kernel<<<BATCH, 256>>>();
    attn_tc_kernel<<<dim3(NPIX / QTILE, BATCH), 256, ATTN_SMEM>>>(x, gamma, out);
}

// round 10
// speedup vs baseline: 1.5204x; 1.1388x over previous
#include <cuda_runtime.h>
#include <cuda_bf16.h>

#define BATCH 8
#define CIN   256
#define DQK   32
#define NPIX  4096   // 64*64
#define NTILE (NPIX / 64)
#define QTILE 128
#define KTILE 64

// Scratch (static device memory: allocation-free rule)
__device__ float g_q  [(size_t)BATCH * NPIX * DQK];  // fp32 q
__device__ float g_khp[(size_t)BATCH * NPIX * DQK];  // paired tf32-hi K
__device__ float g_klp[(size_t)BATCH * NPIX * DQK];  // paired tf32-lo K
__device__ float g_vp [(size_t)BATCH * NPIX * CIN];  // paired tf32 V
__device__ float g_m  [(size_t)BATCH * NPIX];        // |q_i|
__device__ float g_bm [BATCH];                       // max_j |q_j|

// ---------------------------------------------------------------------------
// helpers
// ---------------------------------------------------------------------------
__device__ __forceinline__ unsigned f2tf(float v) {
    unsigned r; asm("cvt.rna.tf32.f32 %0, %1;" : "=r"(r) : "f"(v)); return r;
}
__device__ __forceinline__ float f2tff(float v) {
    return __uint_as_float(f2tf(v));
}
__device__ __forceinline__ void mma8(float d[4], const unsigned a[4],
                                     unsigned b0, unsigned b1) {
    asm volatile(
        "mma.sync.aligned.m16n8k8.row.col.f32.tf32.tf32.f32 "
        "{%0,%1,%2,%3}, {%4,%5,%6,%7}, {%8,%9}, {%0,%1,%2,%3};"
        : "+f"(d[0]), "+f"(d[1]), "+f"(d[2]), "+f"(d[3])
        : "r"(a[0]), "r"(a[1]), "r"(a[2]), "r"(a[3]), "r"(b0), "r"(b1));
}
__device__ __forceinline__ void mma8f(float d[4], const unsigned a[4],
                                      float b0, float b1) {
    mma8(d, a, __float_as_uint(b0), __float_as_uint(b1));
}
__device__ __forceinline__ void cp16(float* smem_dst, const float* gmem_src) {
    unsigned s = (unsigned)__cvta_generic_to_shared(smem_dst);
    asm volatile("cp.async.cg.shared.global [%0], [%1], 16;" :: "r"(s), "l"(gmem_src));
}
#define CP_COMMIT() asm volatile("cp.async.commit_group;")
#define CP_WAIT0()  asm volatile("cp.async.wait_group 0;")

// ---------------------------------------------------------------------------
// Kernel 1: tensor-core fused projection.
// CTA: 64 pixels (blockIdx.x) x 160 outputs (blockIdx.y in {0,1}; o-space
// padded to 320, real outputs 0..287: 0..31 = q, 32..287 = v).
// A = W [o][c] row-major (natural), B = x [c][px] col-major-frag (natural).
// q rows: 3-mma hi/lo split on both operands. v rows: single rna tf32.
// Epilogue writes g_q + paired g_khp/g_klp (q) and paired g_vp (v).
// ---------------------------------------------------------------------------
__global__ __launch_bounds__(256, 2) void proj_tc_kernel(
    const float* __restrict__ x,
    const float* __restrict__ qw, const float* __restrict__ qb,
    const float* __restrict__ vw, const float* __restrict__ vb)
{
    __shared__ float Wa[160][36];   // tf32-hi W chunk [o_local][kk]
    __shared__ float Wl[32][36];    // tf32-lo W (q rows only)
    __shared__ float Xh[32][68];    // tf32-hi x chunk [kk][px]
    __shared__ float Xl[32][68];    // tf32-lo x chunk

    int b  = blockIdx.z;
    int j0 = blockIdx.x * 64;
    int OB = blockIdx.y * 160;

    int tid = threadIdx.x;
    int w    = tid >> 5;
    int lane = tid & 31;
    int g = lane >> 2;
    int t = lane & 3;
    int wr = w >> 2;          // o-row (0..1): 80 outputs
    int wc = w & 3;           // px-col (0..3): 16 pixels
    int obl = wr * 80;        // local output base
    int pxb = wc * 16;        // local pixel base
    bool qwarp = (OB == 0 && wr == 0);

    float acc[5][2][4];
    #pragma unroll
    for (int mi = 0; mi < 5; mi++)
        #pragma unroll
        for (int ni = 0; ni < 2; ni++)
            #pragma unroll
            for (int k = 0; k < 4; k++) acc[mi][ni][k] = 0.f;

    for (int ch = 0; ch < 8; ch++) {
        int c0 = ch * 32;
        __syncthreads();

        // ---- load X chunk [32 c][64 px], hi/lo tf32, natural layout ----
        #pragma unroll
        for (int r = 0; r < 2; r++) {
            int idx = tid + r * 256;        // 512 float4 tasks
            int c   = idx >> 4;
            int pxq = idx & 15;
            float4 v = *(const float4*)(x + ((size_t)b * CIN + c0 + c) * NPIX
                                          + j0 + pxq * 4);
            float4 h, l;
            h.x = f2tff(v.x); l.x = f2tff(v.x - h.x);
            h.y = f2tff(v.y); l.y = f2tff(v.y - h.y);
            h.z = f2tff(v.z); l.z = f2tff(v.z - h.z);
            h.w = f2tff(v.w); l.w = f2tff(v.w - h.w);
            *(float4*)&Xh[c][pxq * 4] = h;
            *(float4*)&Xl[c][pxq * 4] = l;
        }

        // ---- load W chunk [160 o][32 c], hi (+lo for q rows) ----
        #pragma unroll
        for (int r = 0; r < 3; r++) {
            int idx = tid + r * 256;        // 640 tasks (o_l, oct)
            if (idx < 640) {
                int o_l = idx >> 2;
                int oct = idx & 3;
                int o = OB + o_l;
                if (o < 288) {
                    const float* wrow = (o < DQK) ? (qw + (size_t)o * CIN)
                                                  : (vw + (size_t)(o - DQK) * CIN);
                    float4 a4 = *(const float4*)(wrow + c0 + oct * 8);
                    float4 b4 = *(const float4*)(wrow + c0 + oct * 8 + 4);
                    float4 ha, hb;
                    ha.x = f2tff(a4.x); ha.y = f2tff(a4.y);
                    ha.z = f2tff(a4.z); ha.w = f2tff(a4.w);
                    hb.x = f2tff(b4.x); hb.y = f2tff(b4.y);
                    hb.z = f2tff(b4.z); hb.w = f2tff(b4.w);
                    *(float4*)&Wa[o_l][oct * 8]     = ha;
                    *(float4*)&Wa[o_l][oct * 8 + 4] = hb;
                    if (o < DQK) {
                        float4 la, lb;
                        la.x = f2tff(a4.x - ha.x); la.y = f2tff(a4.y - ha.y);
                        la.z = f2tff(a4.z - ha.z); la.w = f2tff(a4.w - ha.w);
                        lb.x = f2tff(b4.x - hb.x); lb.y = f2tff(b4.y - hb.y);
                        lb.z = f2tff(b4.z - hb.z); lb.w = f2tff(b4.w - hb.w);
                        *(float4*)&Wl[o_l][oct * 8]     = la;
                        *(float4*)&Wl[o_l][oct * 8 + 4] = lb;
                    }
                }
            }
        }
        __syncthreads();

        // ---- mma: 4 k8 steps ----
        #pragma unroll
        for (int ks = 0; ks < 4; ks++) {
            float bh[2][2], bl[2][2];
            #pragma unroll
            for (int ni = 0; ni < 2; ni++) {
                int px = pxb + ni * 8 + g;
                bh[ni][0] = Xh[ks * 8 + t][px];
                bh[ni][1] = Xh[ks * 8 + t + 4][px];
                if (qwarp) {
                    bl[ni][0] = Xl[ks * 8 + t][px];
                    bl[ni][1] = Xl[ks * 8 + t + 4][px];
                }
            }
            #pragma unroll
            for (int mi = 0; mi < 5; mi++) {
                if (OB + obl + mi * 16 >= 288) continue;   // padded rows
                int ro = obl + mi * 16 + g;
                unsigned ah[4];
                ah[0] = __float_as_uint(Wa[ro][ks * 8 + t]);
                ah[1] = __float_as_uint(Wa[ro + 8][ks * 8 + t]);
                ah[2] = __float_as_uint(Wa[ro][ks * 8 + t + 4]);
                ah[3] = __float_as_uint(Wa[ro + 8][ks * 8 + t + 4]);
                #pragma unroll
                for (int ni = 0; ni < 2; ni++)
                    mma8f(acc[mi][ni], ah, bh[ni][0], bh[ni][1]);
                if (qwarp && mi < 2) {
                    unsigned al[4];
                    al[0] = __float_as_uint(Wl[ro][ks * 8 + t]);
                    al[1] = __float_as_uint(Wl[ro + 8][ks * 8 + t]);
                    al[2] = __float_as_uint(Wl[ro][ks * 8 + t + 4]);
                    al[3] = __float_as_uint(Wl[ro + 8][ks * 8 + t + 4]);
                    #pragma unroll
                    for (int ni = 0; ni < 2; ni++) {
                        mma8f(acc[mi][ni], ah, bl[ni][0], bl[ni][1]);
                        mma8f(acc[mi][ni], al, bh[ni][0], bh[ni][1]);
                    }
                }
            }
        }
    }

    // ---- epilogue: bias + scatter into g_q / g_khp / g_klp / g_vp ----
    #pragma unroll
    for (int mi = 0; mi < 5; mi++) {
        if (OB + obl + mi * 16 >= 288) continue;
        #pragma unroll
        for (int hh = 0; hh < 2; hh++) {
            int o = OB + obl + mi * 16 + g + 8 * hh;
            if (o >= 288) continue;
            float bias = (o < DQK) ? qb[o] : vb[o - DQK];
            #pragma unroll
            for (int ni = 0; ni < 2; ni++) {
                #pragma unroll
                for (int kk = 0; kk < 2; kk++) {
                    float val = acc[mi][ni][hh * 2 + kk] + bias;
                    int j = j0 + pxb + ni * 8 + 2 * t + kk;
                    if (o < DQK) {
                        g_q[((size_t)b * NPIX + j) * DQK + o] = val;
                        unsigned h = f2tf(val);
                        unsigned l = f2tf(val - __uint_as_float(h));
                        int p = (o >> 3) * 4 + (o & 3);
                        int slot = (o >> 2) & 1;
                        size_t addr = (((size_t)b * NPIX + j) * 16 + p) * 2 + slot;
                        g_khp[addr] = __uint_as_float(h);
                        g_klp[addr] = __uint_as_float(l);
                    } else {
                        int c = o - DQK;
                        int jt = j >> 6;
                        int k6 = j & 63;
                        int tt = k6 & 7;
                        int row = (k6 >> 3) * 4 + (tt & 3);
                        int slot = tt >> 2;
                        size_t addr = ((((size_t)b * NTILE + jt) * 32 + row) * 256
                                       + c) * 2 + slot;
                        g_vp[addr] = f2tff(val);
                    }
                }
            }
        }
    }
}

// ---------------------------------------------------------------------------
// Kernel 2: per-query norms + per-batch max norm (Cauchy-Schwarz bound).
// ---------------------------------------------------------------------------
__global__ __launch_bounds__(256) void qnorm_kernel()
{
    int b = blockIdx.x;
    __shared__ float red[256];
    int tid = threadIdx.x;
    float mx = 0.f;
    for (int i = tid; i < NPIX; i += 256) {
        const float* q = g_q + ((size_t)b * NPIX + i) * DQK;
        float s = 0.f;
        #pragma unroll
        for (int d = 0; d < DQK; d++) s += q[d] * q[d];
        float n = sqrtf(s);
        g_m[(size_t)b * NPIX + i] = n;
        mx = fmaxf(mx, n);
    }
    red[tid] = mx;
    __syncthreads();
    for (int s = 128; s > 0; s >>= 1) {
        if (tid < s) red[tid] = fmaxf(red[tid], red[tid + s]);
        __syncthreads();
    }
    if (tid == 0) g_bm[b] = red[0];
}

// ---------------------------------------------------------------------------
// Kernel 3: tensor-core flash attention (unchanged from R9 / 901us).
// ---------------------------------------------------------------------------
#define KPITCH 20
#define VPITCH 260
#define SM_KH  0
#define SM_KL  20480
#define SM_V   40960
#define SM_PS  174080
#define SM_LB  208896
#define ATTN_SMEM 209408

__global__ __launch_bounds__(256, 1) void attn_tc_kernel(
    const float* __restrict__ x,
    const float* __restrict__ gamma,
    float* __restrict__ out)
{
    extern __shared__ char sm_raw[];
    float* KhS = (float*)(sm_raw + SM_KH);
    float* KlS = (float*)(sm_raw + SM_KL);
    float* VpS = (float*)(sm_raw + SM_V);
    float (*Ps)[68] = (float(*)[68])(sm_raw + SM_PS);
    float* lbuf = (float*)(sm_raw + SM_LB);
    float (*Ot)[132] = (float(*)[132])(sm_raw);

    int b   = blockIdx.y;
    int i0  = blockIdx.x * QTILE;
    int tid = threadIdx.x;
    int w    = tid >> 5;
    int lane = tid & 31;
    int g = lane >> 2;
    int t = lane & 3;
    int q0 = w * 16;
    int qg = w >> 1;
    int cg = w & 1;

    const float* gq_b  = g_q   + (size_t)b * NPIX * DQK;
    const float* gkh_b = g_khp + (size_t)b * NPIX * DQK;
    const float* gkl_b = g_klp + (size_t)b * NPIX * DQK;
    const float* gvp_b = g_vp  + (size_t)b * NPIX * CIN;

    float Mb = g_bm[b];
    float m0 = g_m[(size_t)b * NPIX + i0 + q0 + g] * Mb;
    float m1 = g_m[(size_t)b * NPIX + i0 + q0 + g + 8] * Mb;

    unsigned qh[4][4], ql[4][4];
    #pragma unroll
    for (int kc = 0; kc < 4; kc++) {
        int r0 = i0 + q0 + g, r1 = r0 + 8;
        int c0 = kc * 8 + t,  c1 = c0 + 4;
        float v00 = gq_b[(size_t)r0 * DQK + c0];
        float v10 = gq_b[(size_t)r1 * DQK + c0];
        float v01 = gq_b[(size_t)r0 * DQK + c1];
        float v11 = gq_b[(size_t)r1 * DQK + c1];
        qh[kc][0] = f2tf(v00); ql[kc][0] = f2tf(v00 - __uint_as_float(qh[kc][0]));
        qh[kc][1] = f2tf(v10); ql[kc][1] = f2tf(v10 - __uint_as_float(qh[kc][1]));
        qh[kc][2] = f2tf(v01); ql[kc][2] = f2tf(v01 - __uint_as_float(qh[kc][2]));
        qh[kc][3] = f2tf(v11); ql[kc][3] = f2tf(v11 - __uint_as_float(qh[kc][3]));
    }

    float acc[2][16][4];
    #pragma unroll
    for (int f = 0; f < 2; f++)
        #pragma unroll
        for (int nt = 0; nt < 16; nt++)
            #pragma unroll
            for (int k = 0; k < 4; k++) acc[f][nt][k] = 0.f;
    float l0 = 0.f, l1 = 0.f;

    {
        #pragma unroll
        for (int r = 0; r < 2; r++) {
            int ch = tid + r * 256;
            int key = ch >> 3, c = ch & 7;
            cp16(KhS + key * (KPITCH * 2) + c * 4, gkh_b + (size_t)key * 32 + c * 4);
            cp16(KlS + key * (KPITCH * 2) + c * 4, gkl_b + (size_t)key * 32 + c * 4);
        }
        #pragma unroll
        for (int r = 0; r < 16; r++) {
            int ch = tid + r * 256;
            int row = ch >> 7, c = ch & 127;
            cp16(VpS + row * (VPITCH * 2) + c * 4, gvp_b + (size_t)row * 512 + c * 4);
        }
        CP_COMMIT();
    }

    for (int jt = 0; jt < NTILE; jt++) {
        int buf = jt & 1;
        float* KhB = KhS + buf * (64 * KPITCH * 2);
        float* KlB = KlS + buf * (64 * KPITCH * 2);
        float* VpB = VpS + buf * (32 * VPITCH * 2);

        CP_WAIT0();
        __syncthreads();

        if (jt + 1 < NTILE) {
            int jn = (jt + 1) * KTILE;
            float* KhN = KhS + (1 - buf) * (64 * KPITCH * 2);
            float* KlN = KlS + (1 - buf) * (64 * KPITCH * 2);
            float* VpN = VpS + (1 - buf) * (32 * VPITCH * 2);
            #pragma unroll
            for (int r = 0; r < 2; r++) {
                int ch = tid + r * 256;
                int key = ch >> 3, c = ch & 7;
                cp16(KhN + key * (KPITCH * 2) + c * 4,
                     gkh_b + (size_t)(jn + key) * 32 + c * 4);
                cp16(KlN + key * (KPITCH * 2) + c * 4,
                     gkl_b + (size_t)(jn + key) * 32 + c * 4);
            }
            #pragma unroll
            for (int r = 0; r < 16; r++) {
                int ch = tid + r * 256;
                int row = ch >> 7, c = ch & 127;
                cp16(VpN + row * (VPITCH * 2) + c * 4,
                     gvp_b + (size_t)(jt + 1) * 16384 + (size_t)row * 512 + c * 4);
            }
            CP_COMMIT();
        }

        #pragma unroll
        for (int nt = 0; nt < 8; nt++) {
            float d[4] = {0.f, 0.f, 0.f, 0.f};
            const float2* khrow = (const float2*)KhB + (nt * 8 + g) * KPITCH;
            const float2* klrow = (const float2*)KlB + (nt * 8 + g) * KPITCH;
            #pragma unroll
            for (int kc = 0; kc < 4; kc++) {
                float2 bh = khrow[kc * 4 + t];
                float2 bl = klrow[kc * 4 + t];
                mma8f(d, qh[kc], bh.x, bh.y);
                mma8f(d, qh[kc], bl.x, bl.y);
                mma8f(d, ql[kc], bh.x, bh.y);
            }
            float p0 = __expf(d[0] - m0);
            float p1 = __expf(d[1] - m0);
            float p2 = __expf(d[2] - m1);
            float p3 = __expf(d[3] - m1);
            l0 += p0 + p1;
            l1 += p2 + p3;
            *(float2*)&Ps[q0 + g][nt * 8 + 2 * t]     = make_float2(p0, p1);
            *(float2*)&Ps[q0 + g + 8][nt * 8 + 2 * t] = make_float2(p2, p3);
        }
        __syncthreads();

        #pragma unroll
        for (int kc = 0; kc < 8; kc++) {
            unsigned a[2][4];
            #pragma unroll
            for (int f = 0; f < 2; f++) {
                int rq = qg * 32 + f * 16 + g;
                a[f][0] = __float_as_uint(Ps[rq][kc * 8 + t]);
                a[f][1] = __float_as_uint(Ps[rq + 8][kc * 8 + t]);
                a[f][2] = __float_as_uint(Ps[rq][kc * 8 + t + 4]);
                a[f][3] = __float_as_uint(Ps[rq + 8][kc * 8 + t + 4]);
            }
            const float2* vrow = (const float2*)VpB + (kc * 4 + t) * VPITCH + cg * 128;
            #pragma unroll
            for (int nt = 0; nt < 16; nt++) {
                float2 bv = vrow[nt * 8 + g];
                mma8f(acc[0][nt], a[0], bv.x, bv.y);
                mma8f(acc[1][nt], a[1], bv.x, bv.y);
            }
        }
    }

    l0 += __shfl_xor_sync(0xffffffffu, l0, 1);
    l0 += __shfl_xor_sync(0xffffffffu, l0, 2);
    l1 += __shfl_xor_sync(0xffffffffu, l1, 1);
    l1 += __shfl_xor_sync(0xffffffffu, l1, 2);
    if (t == 0) {
        lbuf[q0 + g]     = 1.f / l0;
        lbuf[q0 + g + 8] = 1.f / l1;
    }
    __syncthreads();

    float inv[2][2];
    #pragma unroll
    for (int f = 0; f < 2; f++) {
        inv[f][0] = lbuf[qg * 32 + f * 16 + g];
        inv[f][1] = lbuf[qg * 32 + f * 16 + g + 8];
    }
    float gam = gamma[0];

    #pragma unroll
    for (int cc = 0; cc < 4; cc++) {
        __syncthreads();
        if (cg == (cc >> 1)) {
            int ntbase = (cc & 1) * 8;
            #pragma unroll
            for (int f = 0; f < 2; f++) {
                int rq = qg * 32 + f * 16 + g;
                #pragma unroll
                for (int ntl = 0; ntl < 8; ntl++) {
                    int nt = ntbase + ntl;
                    int cl = ntl * 8 + 2 * t;
                    Ot[cl][rq]         = acc[f][nt][0] * inv[f][0];
                    Ot[cl + 1][rq]     = acc[f][nt][1] * inv[f][0];
                    Ot[cl][rq + 8]     = acc[f][nt][2] * inv[f][1];
                    Ot[cl + 1][rq + 8] = acc[f][nt][3] * inv[f][1];
                }
            }
        }
        __syncthreads();
        #pragma unroll
        for (int r = 0; r < 8; r++) {
            int idx = tid + r * 256;
            int cl = idx >> 5, q4 = idx & 31;
            int c = cc * 64 + cl;
            size_t base = ((size_t)b * CIN + c) * NPIX + i0 + q4 * 4;
            float4 o = *(float4*)&Ot[cl][q4 * 4];
            float4 xv = *(const float4*)(x + base);
            float4 rv;
            rv.x = gam * o.x + xv.x;
            rv.y = gam * o.y + xv.y;
            rv.z = gam * o.z + xv.z;
            rv.w = gam * o.w + xv.w;
            *(float4*)(out + base) = rv;
        }
    }
}

// ---------------------------------------------------------------------------
extern "C" void kernel_launch(void* const* d_in, const int* in_sizes, int n_in,
                              void* d_out, int out_size)
{
    const float* x     = (const float*)d_in[0];
    const float* q_w   = (const float*)d_in[1];
    const float* q_b   = (const float*)d_in[2];
    const float* v_w   = (const float*)d_in[3];
    const float* v_b   = (const float*)d_in[4];
    const float* gamma = (const float*)d_in[5];
    float* out = (float*)d_out;

    cudaFuncSetAttribute(attn_tc_kernel,
                         cudaFuncAttributeMaxDynamicSharedMemorySize, ATTN_SMEM);

    proj_tc_kernel<<<dim3(NPIX / 64, 2, BATCH), 256>>>(x, q_w, q_b, v_w, v_b);
    qnorm_kernel<<<BATCH, 256>>>();
    attn_tc_kernel<<<dim3(NPIX / QTILE, BATCH), 256, ATTN_SMEM>>>(x, gamma, out);
}

// round 11
// speedup vs baseline: 1.6473x; 1.0835x over previous
#include <cuda_runtime.h>
#include <cuda_bf16.h>

#define BATCH 8
#define CIN   256
#define DQK   32
#define NPIX  4096   // 64*64
#define NTILE (NPIX / 64)
#define QTILE 128
#define KTILE 64

// Scratch (static device memory: allocation-free rule)
__device__ float g_q  [(size_t)BATCH * NPIX * DQK];  // fp32 q
__device__ float g_khp[(size_t)BATCH * NPIX * DQK];  // paired tf32-hi K
__device__ float g_klp[(size_t)BATCH * NPIX * DQK];  // paired tf32-lo K
__device__ float g_vp [(size_t)BATCH * NPIX * CIN];  // paired tf32 V
__device__ float g_m  [(size_t)BATCH * NPIX];        // |q_i|
__device__ float g_bm [BATCH];                       // max_j |q_j|

// ---------------------------------------------------------------------------
// helpers
// ---------------------------------------------------------------------------
__device__ __forceinline__ unsigned f2tf(float v) {
    unsigned r; asm("cvt.rna.tf32.f32 %0, %1;" : "=r"(r) : "f"(v)); return r;
}
__device__ __forceinline__ float f2tff(float v) {
    return __uint_as_float(f2tf(v));
}
__device__ __forceinline__ void mma8(float d[4], const unsigned a[4],
                                     unsigned b0, unsigned b1) {
    asm volatile(
        "mma.sync.aligned.m16n8k8.row.col.f32.tf32.tf32.f32 "
        "{%0,%1,%2,%3}, {%4,%5,%6,%7}, {%8,%9}, {%0,%1,%2,%3};"
        : "+f"(d[0]), "+f"(d[1]), "+f"(d[2]), "+f"(d[3])
        : "r"(a[0]), "r"(a[1]), "r"(a[2]), "r"(a[3]), "r"(b0), "r"(b1));
}
__device__ __forceinline__ void mma8f(float d[4], const unsigned a[4],
                                      float b0, float b1) {
    mma8(d, a, __float_as_uint(b0), __float_as_uint(b1));
}
__device__ __forceinline__ void cp16(float* smem_dst, const float* gmem_src) {
    unsigned s = (unsigned)__cvta_generic_to_shared(smem_dst);
    asm volatile("cp.async.cg.shared.global [%0], [%1], 16;" :: "r"(s), "l"(gmem_src));
}
#define CP_COMMIT() asm volatile("cp.async.commit_group;")
#define CP_WAIT0()  asm volatile("cp.async.wait_group 0;")

// ---------------------------------------------------------------------------
// Kernel 1: tensor-core fused projection (unchanged from R10 / 107us).
// ---------------------------------------------------------------------------
__global__ __launch_bounds__(256, 2) void proj_tc_kernel(
    const float* __restrict__ x,
    const float* __restrict__ qw, const float* __restrict__ qb,
    const float* __restrict__ vw, const float* __restrict__ vb)
{
    __shared__ float Wa[160][36];
    __shared__ float Wl[32][36];
    __shared__ float Xh[32][68];
    __shared__ float Xl[32][68];

    int b  = blockIdx.z;
    int j0 = blockIdx.x * 64;
    int OB = blockIdx.y * 160;

    int tid = threadIdx.x;
    int w    = tid >> 5;
    int lane = tid & 31;
    int g = lane >> 2;
    int t = lane & 3;
    int wr = w >> 2;
    int wc = w & 3;
    int obl = wr * 80;
    int pxb = wc * 16;
    bool qwarp = (OB == 0 && wr == 0);

    float acc[5][2][4];
    #pragma unroll
    for (int mi = 0; mi < 5; mi++)
        #pragma unroll
        for (int ni = 0; ni < 2; ni++)
            #pragma unroll
            for (int k = 0; k < 4; k++) acc[mi][ni][k] = 0.f;

    for (int ch = 0; ch < 8; ch++) {
        int c0 = ch * 32;
        __syncthreads();

        #pragma unroll
        for (int r = 0; r < 2; r++) {
            int idx = tid + r * 256;
            int c   = idx >> 4;
            int pxq = idx & 15;
            float4 v = *(const float4*)(x + ((size_t)b * CIN + c0 + c) * NPIX
                                          + j0 + pxq * 4);
            float4 h, l;
            h.x = f2tff(v.x); l.x = f2tff(v.x - h.x);
            h.y = f2tff(v.y); l.y = f2tff(v.y - h.y);
            h.z = f2tff(v.z); l.z = f2tff(v.z - h.z);
            h.w = f2tff(v.w); l.w = f2tff(v.w - h.w);
            *(float4*)&Xh[c][pxq * 4] = h;
            *(float4*)&Xl[c][pxq * 4] = l;
        }

        #pragma unroll
        for (int r = 0; r < 3; r++) {
            int idx = tid + r * 256;
            if (idx < 640) {
                int o_l = idx >> 2;
                int oct = idx & 3;
                int o = OB + o_l;
                if (o < 288) {
                    const float* wrow = (o < DQK) ? (qw + (size_t)o * CIN)
                                                  : (vw + (size_t)(o - DQK) * CIN);
                    float4 a4 = *(const float4*)(wrow + c0 + oct * 8);
                    float4 b4 = *(const float4*)(wrow + c0 + oct * 8 + 4);
                    float4 ha, hb;
                    ha.x = f2tff(a4.x); ha.y = f2tff(a4.y);
                    ha.z = f2tff(a4.z); ha.w = f2tff(a4.w);
                    hb.x = f2tff(b4.x); hb.y = f2tff(b4.y);
                    hb.z = f2tff(b4.z); hb.w = f2tff(b4.w);
                    *(float4*)&Wa[o_l][oct * 8]     = ha;
                    *(float4*)&Wa[o_l][oct * 8 + 4] = hb;
                    if (o < DQK) {
                        float4 la, lb;
                        la.x = f2tff(a4.x - ha.x); la.y = f2tff(a4.y - ha.y);
                        la.z = f2tff(a4.z - ha.z); la.w = f2tff(a4.w - ha.w);
                        lb.x = f2tff(b4.x - hb.x); lb.y = f2tff(b4.y - hb.y);
                        lb.z = f2tff(b4.z - hb.z); lb.w = f2tff(b4.w - hb.w);
                        *(float4*)&Wl[o_l][oct * 8]     = la;
                        *(float4*)&Wl[o_l][oct * 8 + 4] = lb;
                    }
                }
            }
        }
        __syncthreads();

        #pragma unroll
        for (int ks = 0; ks < 4; ks++) {
            float bh[2][2], bl[2][2];
            #pragma unroll
            for (int ni = 0; ni < 2; ni++) {
                int px = pxb + ni * 8 + g;
                bh[ni][0] = Xh[ks * 8 + t][px];
                bh[ni][1] = Xh[ks * 8 + t + 4][px];
                if (qwarp) {
                    bl[ni][0] = Xl[ks * 8 + t][px];
                    bl[ni][1] = Xl[ks * 8 + t + 4][px];
                }
            }
            #pragma unroll
            for (int mi = 0; mi < 5; mi++) {
                if (OB + obl + mi * 16 >= 288) continue;
                int ro = obl + mi * 16 + g;
                unsigned ah[4];
                ah[0] = __float_as_uint(Wa[ro][ks * 8 + t]);
                ah[1] = __float_as_uint(Wa[ro + 8][ks * 8 + t]);
                ah[2] = __float_as_uint(Wa[ro][ks * 8 + t + 4]);
                ah[3] = __float_as_uint(Wa[ro + 8][ks * 8 + t + 4]);
                #pragma unroll
                for (int ni = 0; ni < 2; ni++)
                    mma8f(acc[mi][ni], ah, bh[ni][0], bh[ni][1]);
                if (qwarp && mi < 2) {
                    unsigned al[4];
                    al[0] = __float_as_uint(Wl[ro][ks * 8 + t]);
                    al[1] = __float_as_uint(Wl[ro + 8][ks * 8 + t]);
                    al[2] = __float_as_uint(Wl[ro][ks * 8 + t + 4]);
                    al[3] = __float_as_uint(Wl[ro + 8][ks * 8 + t + 4]);
                    #pragma unroll
                    for (int ni = 0; ni < 2; ni++) {
                        mma8f(acc[mi][ni], ah, bl[ni][0], bl[ni][1]);
                        mma8f(acc[mi][ni], al, bh[ni][0], bh[ni][1]);
                    }
                }
            }
        }
    }

    #pragma unroll
    for (int mi = 0; mi < 5; mi++) {
        if (OB + obl + mi * 16 >= 288) continue;
        #pragma unroll
        for (int hh = 0; hh < 2; hh++) {
            int o = OB + obl + mi * 16 + g + 8 * hh;
            if (o >= 288) continue;
            float bias = (o < DQK) ? qb[o] : vb[o - DQK];
            #pragma unroll
            for (int ni = 0; ni < 2; ni++) {
                #pragma unroll
                for (int kk = 0; kk < 2; kk++) {
                    float val = acc[mi][ni][hh * 2 + kk] + bias;
                    int j = j0 + pxb + ni * 8 + 2 * t + kk;
                    if (o < DQK) {
                        g_q[((size_t)b * NPIX + j) * DQK + o] = val;
                        unsigned h = f2tf(val);
                        unsigned l = f2tf(val - __uint_as_float(h));
                        int p = (o >> 3) * 4 + (o & 3);
                        int slot = (o >> 2) & 1;
                        size_t addr = (((size_t)b * NPIX + j) * 16 + p) * 2 + slot;
                        g_khp[addr] = __uint_as_float(h);
                        g_klp[addr] = __uint_as_float(l);
                    } else {
                        int c = o - DQK;
                        int jt = j >> 6;
                        int k6 = j & 63;
                        int tt = k6 & 7;
                        int row = (k6 >> 3) * 4 + (tt & 3);
                        int slot = tt >> 2;
                        size_t addr = ((((size_t)b * NTILE + jt) * 32 + row) * 256
                                       + c) * 2 + slot;
                        g_vp[addr] = f2tff(val);
                    }
                }
            }
        }
    }
}

// ---------------------------------------------------------------------------
// Kernel 2: per-query norms + per-batch max norm (Cauchy-Schwarz bound).
// ---------------------------------------------------------------------------
__global__ __launch_bounds__(256) void qnorm_kernel()
{
    int b = blockIdx.x;
    __shared__ float red[256];
    int tid = threadIdx.x;
    float mx = 0.f;
    for (int i = tid; i < NPIX; i += 256) {
        const float* q = g_q + ((size_t)b * NPIX + i) * DQK;
        float s = 0.f;
        #pragma unroll
        for (int d = 0; d < DQK; d++) s += q[d] * q[d];
        float n = sqrtf(s);
        g_m[(size_t)b * NPIX + i] = n;
        mx = fmaxf(mx, n);
    }
    red[tid] = mx;
    __syncthreads();
    for (int s = 128; s > 0; s >>= 1) {
        if (tid < s) red[tid] = fmaxf(red[tid], red[tid + s]);
        __syncthreads();
    }
    if (tid == 0) g_bm[b] = red[0];
}

// ---------------------------------------------------------------------------
// Kernel 3: tensor-core flash attention, 512 threads (4 warps/SMSP).
// Warp w (0..15): queries q0=(w>>1)*16..+16.
//   S-phase : x keys (w&1)*32..+32 (4 nt), partial l per key-half.
//   PV-phase: x channels (w&1)*128..+128, acc = 64 regs.
// Smem: Khp 2x10240 | Klp 2x10240 | Vp 2x66560 | Ps 34816 | lbuf 1024
//     = 209920 B.
// ---------------------------------------------------------------------------
#define KPITCH 20
#define VPITCH 260
#define SM_KH  0
#define SM_KL  20480
#define SM_V   40960
#define SM_PS  174080
#define SM_LB  208896
#define ATTN_SMEM 209920

__global__ __launch_bounds__(512, 1) void attn_tc_kernel(
    const float* __restrict__ x,
    const float* __restrict__ gamma,
    float* __restrict__ out)
{
    extern __shared__ char sm_raw[];
    float* KhS = (float*)(sm_raw + SM_KH);
    float* KlS = (float*)(sm_raw + SM_KL);
    float* VpS = (float*)(sm_raw + SM_V);
    float (*Ps)[68] = (float(*)[68])(sm_raw + SM_PS);
    float* lbuf = (float*)(sm_raw + SM_LB);       // [2][128] partial l
    float (*Ot)[132] = (float(*)[132])(sm_raw);   // epilogue alias

    int b   = blockIdx.y;
    int i0  = blockIdx.x * QTILE;
    int tid = threadIdx.x;
    int w    = tid >> 5;
    int lane = tid & 31;
    int g = lane >> 2;
    int t = lane & 3;
    int q0 = (w >> 1) * 16;   // query base (S and PV)
    int hf = w & 1;           // key half (S) / channel half (PV)
    int kb = hf * 32;         // S-phase key base
    int cb = hf * 128;        // PV channel base

    const float* gq_b  = g_q   + (size_t)b * NPIX * DQK;
    const float* gkh_b = g_khp + (size_t)b * NPIX * DQK;
    const float* gkl_b = g_klp + (size_t)b * NPIX * DQK;
    const float* gvp_b = g_vp  + (size_t)b * NPIX * CIN;

    float Mb = g_bm[b];
    float m0 = g_m[(size_t)b * NPIX + i0 + q0 + g] * Mb;
    float m1 = g_m[(size_t)b * NPIX + i0 + q0 + g + 8] * Mb;

    // persistent Q fragments (hi/lo tf32 split)
    unsigned qh[4][4], ql[4][4];
    #pragma unroll
    for (int kc = 0; kc < 4; kc++) {
        int r0 = i0 + q0 + g, r1 = r0 + 8;
        int c0 = kc * 8 + t,  c1 = c0 + 4;
        float v00 = gq_b[(size_t)r0 * DQK + c0];
        float v10 = gq_b[(size_t)r1 * DQK + c0];
        float v01 = gq_b[(size_t)r0 * DQK + c1];
        float v11 = gq_b[(size_t)r1 * DQK + c1];
        qh[kc][0] = f2tf(v00); ql[kc][0] = f2tf(v00 - __uint_as_float(qh[kc][0]));
        qh[kc][1] = f2tf(v10); ql[kc][1] = f2tf(v10 - __uint_as_float(qh[kc][1]));
        qh[kc][2] = f2tf(v01); ql[kc][2] = f2tf(v01 - __uint_as_float(qh[kc][2]));
        qh[kc][3] = f2tf(v11); ql[kc][3] = f2tf(v11 - __uint_as_float(qh[kc][3]));
    }

    float acc[16][4];
    #pragma unroll
    for (int nt = 0; nt < 16; nt++)
        #pragma unroll
        for (int k = 0; k < 4; k++) acc[nt][k] = 0.f;
    float l0 = 0.f, l1 = 0.f;

    // ---- prefetch tile 0 into buffer 0 ----
    {
        {
            int key = tid >> 3, c = tid & 7;    // 512 tasks
            cp16(KhS + key * (KPITCH * 2) + c * 4, gkh_b + (size_t)key * 32 + c * 4);
            cp16(KlS + key * (KPITCH * 2) + c * 4, gkl_b + (size_t)key * 32 + c * 4);
        }
        #pragma unroll
        for (int r = 0; r < 8; r++) {
            int ch = tid + r * 512;             // 4096 tasks
            int row = ch >> 7, c = ch & 127;
            cp16(VpS + row * (VPITCH * 2) + c * 4, gvp_b + (size_t)row * 512 + c * 4);
        }
        CP_COMMIT();
    }

    for (int jt = 0; jt < NTILE; jt++) {
        int buf = jt & 1;
        float* KhB = KhS + buf * (64 * KPITCH * 2);
        float* KlB = KlS + buf * (64 * KPITCH * 2);
        float* VpB = VpS + buf * (32 * VPITCH * 2);

        CP_WAIT0();
        __syncthreads();

        // ---- prefetch tile jt+1 ----
        if (jt + 1 < NTILE) {
            int jn = (jt + 1) * KTILE;
            float* KhN = KhS + (1 - buf) * (64 * KPITCH * 2);
            float* KlN = KlS + (1 - buf) * (64 * KPITCH * 2);
            float* VpN = VpS + (1 - buf) * (32 * VPITCH * 2);
            {
                int key = tid >> 3, c = tid & 7;
                cp16(KhN + key * (KPITCH * 2) + c * 4,
                     gkh_b + (size_t)(jn + key) * 32 + c * 4);
                cp16(KlN + key * (KPITCH * 2) + c * 4,
                     gkl_b + (size_t)(jn + key) * 32 + c * 4);
            }
            #pragma unroll
            for (int r = 0; r < 8; r++) {
                int ch = tid + r * 512;
                int row = ch >> 7, c = ch & 127;
                cp16(VpN + row * (VPITCH * 2) + c * 4,
                     gvp_b + (size_t)(jt + 1) * 16384 + (size_t)row * 512 + c * 4);
            }
            CP_COMMIT();
        }

        // ---- S = Q K^T over this warp's 32-key half, P = exp(S-m) ----
        #pragma unroll
        for (int nt = 0; nt < 4; nt++) {
            float d[4] = {0.f, 0.f, 0.f, 0.f};
            const float2* khrow = (const float2*)KhB + (kb + nt * 8 + g) * KPITCH;
            const float2* klrow = (const float2*)KlB + (kb + nt * 8 + g) * KPITCH;
            #pragma unroll
            for (int kc = 0; kc < 4; kc++) {
                float2 bh = khrow[kc * 4 + t];
                float2 bl = klrow[kc * 4 + t];
                mma8f(d, qh[kc], bh.x, bh.y);
                mma8f(d, qh[kc], bl.x, bl.y);
                mma8f(d, ql[kc], bh.x, bh.y);
            }
            float p0 = __expf(d[0] - m0);
            float p1 = __expf(d[1] - m0);
            float p2 = __expf(d[2] - m1);
            float p3 = __expf(d[3] - m1);
            l0 += p0 + p1;
            l1 += p2 + p3;
            *(float2*)&Ps[q0 + g][kb + nt * 8 + 2 * t]     = make_float2(p0, p1);
            *(float2*)&Ps[q0 + g + 8][kb + nt * 8 + 2 * t] = make_float2(p2, p3);
        }
        __syncthreads();

        // ---- O += P V : 16q x 128c per warp ----
        #pragma unroll
        for (int kc = 0; kc < 8; kc++) {
            unsigned a[4];
            a[0] = __float_as_uint(Ps[q0 + g][kc * 8 + t]);
            a[1] = __float_as_uint(Ps[q0 + g + 8][kc * 8 + t]);
            a[2] = __float_as_uint(Ps[q0 + g][kc * 8 + t + 4]);
            a[3] = __float_as_uint(Ps[q0 + g + 8][kc * 8 + t + 4]);
            const float2* vrow = (const float2*)VpB + (kc * 4 + t) * VPITCH + cb;
            #pragma unroll
            for (int nt = 0; nt < 16; nt++) {
                float2 bv = vrow[nt * 8 + g];
                mma8f(acc[nt], a, bv.x, bv.y);
            }
        }
    }

    // ---- l reduction: quad lanes, then combine the two key-half partials ----
    l0 += __shfl_xor_sync(0xffffffffu, l0, 1);
    l0 += __shfl_xor_sync(0xffffffffu, l0, 2);
    l1 += __shfl_xor_sync(0xffffffffu, l1, 1);
    l1 += __shfl_xor_sync(0xffffffffu, l1, 2);
    if (t == 0) {
        lbuf[hf * 128 + q0 + g]     = l0;
        lbuf[hf * 128 + q0 + g + 8] = l1;
    }
    __syncthreads();

    float inv0 = 1.f / (lbuf[q0 + g]     + lbuf[128 + q0 + g]);
    float inv1 = 1.f / (lbuf[q0 + g + 8] + lbuf[128 + q0 + g + 8]);
    float gam = gamma[0];

    // ---- epilogue: 4 chunks of 64 channels ----
    #pragma unroll
    for (int cc = 0; cc < 4; cc++) {
        __syncthreads();
        if (hf == (cc >> 1)) {
            int ntbase = (cc & 1) * 8;
            #pragma unroll
            for (int ntl = 0; ntl < 8; ntl++) {
                int nt = ntbase + ntl;
                int cl = ntl * 8 + 2 * t;
                Ot[cl][q0 + g]         = acc[nt][0] * inv0;
                Ot[cl + 1][q0 + g]     = acc[nt][1] * inv0;
                Ot[cl][q0 + g + 8]     = acc[nt][2] * inv1;
                Ot[cl + 1][q0 + g + 8] = acc[nt][3] * inv1;
            }
        }
        __syncthreads();
        #pragma unroll
        for (int r = 0; r < 4; r++) {
            int idx = tid + r * 512;
            int cl = idx >> 5, q4 = idx & 31;
            int c = cc * 64 + cl;
            size_t base = ((size_t)b * CIN + c) * NPIX + i0 + q4 * 4;
            float4 o = *(float4*)&Ot[cl][q4 * 4];
            float4 xv = *(const float4*)(x + base);
            float4 rv;
            rv.x = gam * o.x + xv.x;
            rv.y = gam * o.y + xv.y;
            rv.z = gam * o.z + xv.z;
            rv.w = gam * o.w + xv.w;
            *(float4*)(out + base) = rv;
        }
    }
}

// ---------------------------------------------------------------------------
extern "C" void kernel_launch(void* const* d_in, const int* in_sizes, int n_in,
                              void* d_out, int out_size)
{
    const float* x     = (const float*)d_in[0];
    const float* q_w   = (const float*)d_in[1];
    const float* q_b   = (const float*)d_in[2];
    const float* v_w   = (const float*)d_in[3];
    const float* v_b   = (const float*)d_in[4];
    const float* gamma = (const float*)d_in[5];
    float* out = (float*)d_out;

    cudaFuncSetAttribute(attn_tc_kernel,
                         cudaFuncAttributeMaxDynamicSharedMemorySize, ATTN_SMEM);

    proj_tc_kernel<<<dim3(NPIX / 64, 2, BATCH), 256>>>(x, q_w, q_b, v_w, v_b);
    qnorm_kernel<<<BATCH, 256>>>();
    attn_tc_kernel<<<dim3(NPIX / QTILE, BATCH), 512, ATTN_SMEM>>>(x, gamma, out);
}

// round 15
// speedup vs baseline: 2.4951x; 1.5146x over previous
#include <cuda_runtime.h>
#include <cuda_fp16.h>
#include <cuda_bf16.h>

#define BATCH 8
#define CIN   256
#define DQK   32
#define NPIX  4096   // 64*64
#define NTILE (NPIX / 64)
#define QTILE 128
#define KTILE 64

// Scratch (static device memory: allocation-free rule)
__device__ float  g_q  [(size_t)BATCH * NPIX * DQK];  // fp32 q
__device__ __half g_khp[(size_t)BATCH * NPIX * DQK];  // packed fp16-hi K frags
__device__ __half g_klp[(size_t)BATCH * NPIX * DQK];  // packed fp16-lo K frags
__device__ __half g_vp [(size_t)BATCH * NPIX * CIN];  // packed fp16 V frags
__device__ float  g_m  [(size_t)BATCH * NPIX];        // |q_i|
__device__ float  g_bm [BATCH];                       // max_j |q_j|

// ---------------------------------------------------------------------------
// helpers
// ---------------------------------------------------------------------------
__device__ __forceinline__ unsigned f2tf(float v) {
    unsigned r; asm("cvt.rna.tf32.f32 %0, %1;" : "=r"(r) : "f"(v)); return r;
}
__device__ __forceinline__ float f2tff(float v) {
    return __uint_as_float(f2tf(v));
}
// tf32 k8 mma (proj kernel only)
__device__ __forceinline__ void mma8(float d[4], const unsigned a[4],
                                     unsigned b0, unsigned b1) {
    asm volatile(
        "mma.sync.aligned.m16n8k8.row.col.f32.tf32.tf32.f32 "
        "{%0,%1,%2,%3}, {%4,%5,%6,%7}, {%8,%9}, {%0,%1,%2,%3};"
        : "+f"(d[0]), "+f"(d[1]), "+f"(d[2]), "+f"(d[3])
        : "r"(a[0]), "r"(a[1]), "r"(a[2]), "r"(a[3]), "r"(b0), "r"(b1));
}
__device__ __forceinline__ void mma8f(float d[4], const unsigned a[4],
                                      float b0, float b1) {
    mma8(d, a, __float_as_uint(b0), __float_as_uint(b1));
}
// fp16 k16 mma (attention)
__device__ __forceinline__ void mma16(float d[4], const unsigned a[4],
                                      unsigned b0, unsigned b1) {
    asm volatile(
        "mma.sync.aligned.m16n8k16.row.col.f32.f16.f16.f32 "
        "{%0,%1,%2,%3}, {%4,%5,%6,%7}, {%8,%9}, {%0,%1,%2,%3};"
        : "+f"(d[0]), "+f"(d[1]), "+f"(d[2]), "+f"(d[3])
        : "r"(a[0]), "r"(a[1]), "r"(a[2]), "r"(a[3]), "r"(b0), "r"(b1));
}
__device__ __forceinline__ void cp16(void* smem_dst, const void* gmem_src) {
    unsigned s = (unsigned)__cvta_generic_to_shared(smem_dst);
    asm volatile("cp.async.cg.shared.global [%0], [%1], 16;" :: "r"(s), "l"(gmem_src));
}
#define CP_COMMIT() asm volatile("cp.async.commit_group;")
#define CP_WAIT0()  asm volatile("cp.async.wait_group 0;")

__device__ __forceinline__ unsigned pack_h2(float a, float b) {
    __half2 h = __floats2half2_rn(a, b);
    return *(unsigned*)&h;
}

// K/V fragment packing index: within a k16 chunk, slot row tt holds k-values
// {2tt, 2tt+1, 2tt+8, 2tt+9} as 4 consecutive halves (elem 0..3).
__device__ __forceinline__ void frag_pos(int k15, int& tt, int& elem) {
    int pos8 = k15 >> 3;
    tt   = (k15 >> 1) & 3;
    elem = (k15 & 1) + 2 * pos8;
}

// ---------------------------------------------------------------------------
// Kernel 1: tensor-core fused projection (epilogue writes packed fp16
// layouts).  K: 8 slots/tile, tile stride 2048 halves.  V: 16 slots/tile,
// tile stride 16384 halves.
// ---------------------------------------------------------------------------
__global__ __launch_bounds__(256, 2) void proj_tc_kernel(
    const float* __restrict__ x,
    const float* __restrict__ qw, const float* __restrict__ qb,
    const float* __restrict__ vw, const float* __restrict__ vb)
{
    __shared__ float Wa[160][36];
    __shared__ float Wl[32][36];
    __shared__ float Xh[32][68];
    __shared__ float Xl[32][68];

    int b  = blockIdx.z;
    int j0 = blockIdx.x * 64;
    int OB = blockIdx.y * 160;

    int tid = threadIdx.x;
    int w    = tid >> 5;
    int lane = tid & 31;
    int g = lane >> 2;
    int t = lane & 3;
    int wr = w >> 2;
    int wc = w & 3;
    int obl = wr * 80;
    int pxb = wc * 16;
    bool qwarp = (OB == 0 && wr == 0);

    float acc[5][2][4];
    #pragma unroll
    for (int mi = 0; mi < 5; mi++)
        #pragma unroll
        for (int ni = 0; ni < 2; ni++)
            #pragma unroll
            for (int k = 0; k < 4; k++) acc[mi][ni][k] = 0.f;

    for (int ch = 0; ch < 8; ch++) {
        int c0 = ch * 32;
        __syncthreads();

        #pragma unroll
        for (int r = 0; r < 2; r++) {
            int idx = tid + r * 256;
            int c   = idx >> 4;
            int pxq = idx & 15;
            float4 v = *(const float4*)(x + ((size_t)b * CIN + c0 + c) * NPIX
                                          + j0 + pxq * 4);
            float4 h, l;
            h.x = f2tff(v.x); l.x = f2tff(v.x - h.x);
            h.y = f2tff(v.y); l.y = f2tff(v.y - h.y);
            h.z = f2tff(v.z); l.z = f2tff(v.z - h.z);
            h.w = f2tff(v.w); l.w = f2tff(v.w - h.w);
            *(float4*)&Xh[c][pxq * 4] = h;
            *(float4*)&Xl[c][pxq * 4] = l;
        }

        #pragma unroll
        for (int r = 0; r < 3; r++) {
            int idx = tid + r * 256;
            if (idx < 640) {
                int o_l = idx >> 2;
                int oct = idx & 3;
                int o = OB + o_l;
                if (o < 288) {
                    const float* wrow = (o < DQK) ? (qw + (size_t)o * CIN)
                                                  : (vw + (size_t)(o - DQK) * CIN);
                    float4 a4 = *(const float4*)(wrow + c0 + oct * 8);
                    float4 b4 = *(const float4*)(wrow + c0 + oct * 8 + 4);
                    float4 ha, hb;
                    ha.x = f2tff(a4.x); ha.y = f2tff(a4.y);
                    ha.z = f2tff(a4.z); ha.w = f2tff(a4.w);
                    hb.x = f2tff(b4.x); hb.y = f2tff(b4.y);
                    hb.z = f2tff(b4.z); hb.w = f2tff(b4.w);
                    *(float4*)&Wa[o_l][oct * 8]     = ha;
                    *(float4*)&Wa[o_l][oct * 8 + 4] = hb;
                    if (o < DQK) {
                        float4 la, lb;
                        la.x = f2tff(a4.x - ha.x); la.y = f2tff(a4.y - ha.y);
                        la.z = f2tff(a4.z - ha.z); la.w = f2tff(a4.w - ha.w);
                        lb.x = f2tff(b4.x - hb.x); lb.y = f2tff(b4.y - hb.y);
                        lb.z = f2tff(b4.z - hb.z); lb.w = f2tff(b4.w - hb.w);
                        *(float4*)&Wl[o_l][oct * 8]     = la;
                        *(float4*)&Wl[o_l][oct * 8 + 4] = lb;
                    }
                }
            }
        }
        __syncthreads();

        #pragma unroll
        for (int ks = 0; ks < 4; ks++) {
            float bh[2][2], bl[2][2];
            #pragma unroll
            for (int ni = 0; ni < 2; ni++) {
                int px = pxb + ni * 8 + g;
                bh[ni][0] = Xh[ks * 8 + t][px];
                bh[ni][1] = Xh[ks * 8 + t + 4][px];
                if (qwarp) {
                    bl[ni][0] = Xl[ks * 8 + t][px];
                    bl[ni][1] = Xl[ks * 8 + t + 4][px];
                }
            }
            #pragma unroll
            for (int mi = 0; mi < 5; mi++) {
                if (OB + obl + mi * 16 >= 288) continue;
                int ro = obl + mi * 16 + g;
                unsigned ah[4];
                ah[0] = __float_as_uint(Wa[ro][ks * 8 + t]);
                ah[1] = __float_as_uint(Wa[ro + 8][ks * 8 + t]);
                ah[2] = __float_as_uint(Wa[ro][ks * 8 + t + 4]);
                ah[3] = __float_as_uint(Wa[ro + 8][ks * 8 + t + 4]);
                #pragma unroll
                for (int ni = 0; ni < 2; ni++)
                    mma8f(acc[mi][ni], ah, bh[ni][0], bh[ni][1]);
                if (qwarp && mi < 2) {
                    unsigned al[4];
                    al[0] = __float_as_uint(Wl[ro][ks * 8 + t]);
                    al[1] = __float_as_uint(Wl[ro + 8][ks * 8 + t]);
                    al[2] = __float_as_uint(Wl[ro][ks * 8 + t + 4]);
                    al[3] = __float_as_uint(Wl[ro + 8][ks * 8 + t + 4]);
                    #pragma unroll
                    for (int ni = 0; ni < 2; ni++) {
                        mma8f(acc[mi][ni], ah, bl[ni][0], bl[ni][1]);
                        mma8f(acc[mi][ni], al, bh[ni][0], bh[ni][1]);
                    }
                }
            }
        }
    }

    #pragma unroll
    for (int mi = 0; mi < 5; mi++) {
        if (OB + obl + mi * 16 >= 288) continue;
        #pragma unroll
        for (int hh = 0; hh < 2; hh++) {
            int o = OB + obl + mi * 16 + g + 8 * hh;
            if (o >= 288) continue;
            float bias = (o < DQK) ? qb[o] : vb[o - DQK];
            #pragma unroll
            for (int ni = 0; ni < 2; ni++) {
                #pragma unroll
                for (int kk = 0; kk < 2; kk++) {
                    float val = acc[mi][ni][hh * 2 + kk] + bias;
                    int j = j0 + pxb + ni * 8 + 2 * t + kk;
                    int jt = j >> 6;
                    int key = j & 63;
                    if (o < DQK) {
                        g_q[((size_t)b * NPIX + j) * DQK + o] = val;
                        __half hq = __float2half_rn(val);
                        __half lq = __float2half_rn(val - __half2float(hq));
                        int kc = o >> 4, tt, elem;
                        frag_pos(o & 15, tt, elem);
                        int slot = kc * 4 + tt;            // 0..7
                        size_t idx = ((((size_t)b * NTILE + jt) * 8 + slot) * 64
                                      + key) * 4 + elem;
                        g_khp[idx] = hq;
                        g_klp[idx] = lq;
                    } else {
                        int c = o - DQK;
                        int kc = key >> 4, tt, elem;
                        frag_pos(key & 15, tt, elem);
                        int slot = kc * 4 + tt;            // 0..15
                        size_t idx = ((((size_t)b * NTILE + jt) * 16 + slot) * 256
                                      + c) * 4 + elem;
                        g_vp[idx] = __float2half_rn(val);
                    }
                }
            }
        }
    }
}

// ---------------------------------------------------------------------------
// Kernel 2: per-query norms + per-batch max norm.
// ---------------------------------------------------------------------------
__global__ __launch_bounds__(256) void qnorm_kernel()
{
    int b = blockIdx.x;
    __shared__ float red[256];
    int tid = threadIdx.x;
    float mx = 0.f;
    for (int i = tid; i < NPIX; i += 256) {
        const float* q = g_q + ((size_t)b * NPIX + i) * DQK;
        float s = 0.f;
        #pragma unroll
        for (int d = 0; d < DQK; d++) s += q[d] * q[d];
        float n = sqrtf(s);
        g_m[(size_t)b * NPIX + i] = n;
        mx = fmaxf(mx, n);
    }
    red[tid] = mx;
    __syncthreads();
    for (int s = 128; s > 0; s >>= 1) {
        if (tid < s) red[tid] = fmaxf(red[tid], red[tid + s]);
        __syncthreads();
    }
    if (tid == 0) g_bm[b] = red[0];
}

// ---------------------------------------------------------------------------
// Kernel 3: fp16 tensor-core flash attention, 512 threads.
// Softmax shift: m_i = |q_i| * (M + |q_i|) / 2  (midpoint between the
// Cauchy-Schwarz upper bound and the diagonal lower bound) so that the
// fp16-stored p stays within [exp(-M^2/8), exp(M^2/8)] — no under/overflow.
// ---------------------------------------------------------------------------
#define KROWB  544    // K smem row pitch bytes (512 payload + 32)
#define VROWB  2080   // V smem row pitch bytes (2048 payload + 32)
#define KBUF   (8 * KROWB)
#define VBUF   (16 * VROWB)
#define PSPITCH 72    // halves per Ps row
#define SM_KH  0
#define SM_KL  (2 * KBUF)
#define SM_V   (4 * KBUF)
#define SM_PS  (SM_V + 2 * VBUF)
#define SM_LB  (SM_PS + 128 * PSPITCH * 2)
#define ATTN_SMEM (SM_LB + 1024)

__global__ __launch_bounds__(512, 1) void attn_tc_kernel(
    const float* __restrict__ x,
    const float* __restrict__ gamma,
    float* __restrict__ out)
{
    extern __shared__ char sm_raw[];
    char* KhS = sm_raw + SM_KH;
    char* KlS = sm_raw + SM_KL;
    char* VpS = sm_raw + SM_V;
    __half* PsH = (__half*)(sm_raw + SM_PS);
    float* lbuf = (float*)(sm_raw + SM_LB);
    float (*Ot)[132] = (float(*)[132])(sm_raw);   // epilogue alias

    int b   = blockIdx.y;
    int i0  = blockIdx.x * QTILE;
    int tid = threadIdx.x;
    int w    = tid >> 5;
    int lane = tid & 31;
    int g = lane >> 2;
    int t = lane & 3;
    int q0 = (w >> 1) * 16;   // query base
    int hf = w & 1;           // key half (S) / channel half (PV)
    int kb = hf * 32;         // S-phase key base
    int cb = hf * 128;        // PV channel base

    const float*  gq_b  = g_q   + (size_t)b * NPIX * DQK;
    const __half* gkh_b = g_khp + (size_t)b * NPIX * DQK;
    const __half* gkl_b = g_klp + (size_t)b * NPIX * DQK;
    const __half* gvp_b = g_vp  + (size_t)b * NPIX * CIN;

    float Mb = g_bm[b];
    float n0 = g_m[(size_t)b * NPIX + i0 + q0 + g];
    float n1 = g_m[(size_t)b * NPIX + i0 + q0 + g + 8];
    // midpoint shift: keeps fp16 p in [exp(-M^2/8), exp(M^2/8)]
    float m0 = n0 * (Mb + n0) * 0.5f;
    float m1 = n1 * (Mb + n1) * 0.5f;

    // persistent Q fragments, fp16 hi/lo, 2 k16 chunks
    unsigned qh[2][4], ql[2][4];
    #pragma unroll
    for (int kc = 0; kc < 2; kc++) {
        int r0 = i0 + q0 + g, r1 = r0 + 8;
        int c0 = kc * 16 + 2 * t;       // cols c0, c0+1
        int c2 = c0 + 8;                // cols c2, c2+1
        #pragma unroll
        for (int e = 0; e < 4; e++) {
            int row = (e & 1) ? r1 : r0;
            int col = (e & 2) ? c2 : c0;
            float va = gq_b[(size_t)row * DQK + col];
            float vb2 = gq_b[(size_t)row * DQK + col + 1];
            __half ha = __float2half_rn(va);
            __half hb = __float2half_rn(vb2);
            float la = va - __half2float(ha);
            float lb = vb2 - __half2float(hb);
            __half2 hp = __halves2half2(ha, hb);
            __half2 lp = __halves2half2(__float2half_rn(la), __float2half_rn(lb));
            qh[kc][e] = *(unsigned*)&hp;
            ql[kc][e] = *(unsigned*)&lp;
        }
    }

    float acc[16][4];
    #pragma unroll
    for (int nt = 0; nt < 16; nt++)
        #pragma unroll
        for (int k = 0; k < 4; k++) acc[nt][k] = 0.f;
    float l0 = 0.f, l1 = 0.f;

    // ---- prefetch tile 0 into buffer 0 ----
    {
        // K: 256 chunks per array; threads 0..255 -> Kh, 256..511 -> Kl
        int c = tid & 255, arr = tid >> 8;
        int slot = c >> 5, chunk = c & 31;
        const __half* src = (arr ? gkl_b : gkh_b) + slot * 256 + chunk * 8;
        char* dst = (arr ? KlS : KhS) + slot * KROWB + chunk * 16;
        cp16(dst, src);
        #pragma unroll
        for (int r = 0; r < 4; r++) {
            int ch = tid + r * 512;             // 2048 V tasks
            int vs = ch >> 7, vc = ch & 127;
            cp16(VpS + vs * VROWB + vc * 16, gvp_b + vs * 1024 + vc * 8);
        }
        CP_COMMIT();
    }

    for (int jt = 0; jt < NTILE; jt++) {
        int buf = jt & 1;
        char* KhB = KhS + buf * KBUF;
        char* KlB = KlS + buf * KBUF;
        char* VpB = VpS + buf * VBUF;

        CP_WAIT0();
        __syncthreads();

        // ---- prefetch tile jt+1 ----
        if (jt + 1 < NTILE) {
            char* KhN = KhS + (1 - buf) * KBUF;
            char* KlN = KlS + (1 - buf) * KBUF;
            char* VpN = VpS + (1 - buf) * VBUF;
            const __half* kh_t = gkh_b + (size_t)(jt + 1) * 2048;
            const __half* kl_t = gkl_b + (size_t)(jt + 1) * 2048;
            const __half* vp_t = gvp_b + (size_t)(jt + 1) * 16384;
            int c = tid & 255, arr = tid >> 8;
            int slot = c >> 5, chunk = c & 31;
            const __half* src = (arr ? kl_t : kh_t) + slot * 256 + chunk * 8;
            char* dst = (arr ? KlN : KhN) + slot * KROWB + chunk * 16;
            cp16(dst, src);
            #pragma unroll
            for (int r = 0; r < 4; r++) {
                int ch = tid + r * 512;
                int vs = ch >> 7, vc = ch & 127;
                cp16(VpN + vs * VROWB + vc * 16, vp_t + vs * 1024 + vc * 8);
            }
            CP_COMMIT();
        }

        // ---- S = Q K^T (fp16 3-mma split), P = exp(S-m) -> Ps (fp16) ----
        #pragma unroll
        for (int nt = 0; nt < 4; nt++) {
            float d4[4] = {0.f, 0.f, 0.f, 0.f};
            #pragma unroll
            for (int kc = 0; kc < 2; kc++) {
                const char* kaddr = KhB + (kc * 4 + t) * KROWB + (kb + nt * 8 + g) * 8;
                const char* laddr = KlB + (kc * 4 + t) * KROWB + (kb + nt * 8 + g) * 8;
                uint2 bh = *(const uint2*)kaddr;
                uint2 bl = *(const uint2*)laddr;
                mma16(d4, qh[kc], bh.x, bh.y);
                mma16(d4, qh[kc], bl.x, bl.y);
                mma16(d4, ql[kc], bh.x, bh.y);
            }
            float p0 = fminf(__expf(d4[0] - m0), 60000.f);
            float p1 = fminf(__expf(d4[1] - m0), 60000.f);
            float p2 = fminf(__expf(d4[2] - m1), 60000.f);
            float p3 = fminf(__expf(d4[3] - m1), 60000.f);
            l0 += p0 + p1;
            l1 += p2 + p3;
            int col = kb + nt * 8 + 2 * t;
            *(unsigned*)&PsH[(q0 + g) * PSPITCH + col]     = pack_h2(p0, p1);
            *(unsigned*)&PsH[(q0 + g + 8) * PSPITCH + col] = pack_h2(p2, p3);
        }
        __syncthreads();

        // ---- O += P V : fp16 k16, 16q x 128c per warp ----
        #pragma unroll
        for (int kc = 0; kc < 4; kc++) {
            unsigned a[4];
            const __half* pr0 = PsH + (q0 + g) * PSPITCH + kc * 16;
            const __half* pr1 = PsH + (q0 + g + 8) * PSPITCH + kc * 16;
            a[0] = *(const unsigned*)(pr0 + 2 * t);
            a[1] = *(const unsigned*)(pr1 + 2 * t);
            a[2] = *(const unsigned*)(pr0 + 2 * t + 8);
            a[3] = *(const unsigned*)(pr1 + 2 * t + 8);
            const char* vrow = VpB + (kc * 4 + t) * VROWB + cb * 8;
            #pragma unroll
            for (int nt = 0; nt < 16; nt++) {
                uint2 bv = *(const uint2*)(vrow + (nt * 8 + g) * 8);
                mma16(acc[nt], a, bv.x, bv.y);
            }
        }
    }

    // ---- l reduction: quad lanes, then combine the two key-half partials ----
    l0 += __shfl_xor_sync(0xffffffffu, l0, 1);
    l0 += __shfl_xor_sync(0xffffffffu, l0, 2);
    l1 += __shfl_xor_sync(0xffffffffu, l1, 1);
    l1 += __shfl_xor_sync(0xffffffffu, l1, 2);
    if (t == 0) {
        lbuf[hf * 128 + q0 + g]     = l0;
        lbuf[hf * 128 + q0 + g + 8] = l1;
    }
    __syncthreads();

    float inv0 = 1.f / (lbuf[q0 + g]     + lbuf[128 + q0 + g]);
    float inv1 = 1.f / (lbuf[q0 + g + 8] + lbuf[128 + q0 + g + 8]);
    float gam = gamma[0];

    // ---- epilogue: 4 chunks of 64 channels ----
    #pragma unroll
    for (int cc = 0; cc < 4; cc++) {
        __syncthreads();
        if (hf == (cc >> 1)) {
            int ntbase = (cc & 1) * 8;
            #pragma unroll
            for (int ntl = 0; ntl < 8; ntl++) {
                int nt = ntbase + ntl;
                int cl = ntl * 8 + 2 * t;
                Ot[cl][q0 + g]         = acc[nt][0] * inv0;
                Ot[cl + 1][q0 + g]     = acc[nt][1] * inv0;
                Ot[cl][q0 + g + 8]     = acc[nt][2] * inv1;
                Ot[cl + 1][q0 + g + 8] = acc[nt][3] * inv1;
            }
        }
        __syncthreads();
        #pragma unroll
        for (int r = 0; r < 4; r++) {
            int idx = tid + r * 512;
            int cl = idx >> 5, q4 = idx & 31;
            int c = cc * 64 + cl;
            size_t base = ((size_t)b * CIN + c) * NPIX + i0 + q4 * 4;
            float4 o = *(float4*)&Ot[cl][q4 * 4];
            float4 xv = *(const float4*)(x + base);
            float4 rv;
            rv.x = gam * o.x + xv.x;
            rv.y = gam * o.y + xv.y;
            rv.z = gam * o.z + xv.z;
            rv.w = gam * o.w + xv.w;
            *(float4*)(out + base) = rv;
        }
    }
}

// ---------------------------------------------------------------------------
extern "C" void kernel_launch(void* const* d_in, const int* in_sizes, int n_in,
                              void* d_out, int out_size)
{
    const float* x     = (const float*)d_in[0];
    const float* q_w   = (const float*)d_in[1];
    const float* q_b   = (const float*)d_in[2];
    const float* v_w   = (const float*)d_in[3];
    const float* v_b   = (const float*)d_in[4];
    const float* gamma = (const float*)d_in[5];
    float* out = (float*)d_out;

    cudaFuncSetAttribute(attn_tc_kernel,
                         cudaFuncAttributeMaxDynamicSharedMemorySize, ATTN_SMEM);

    proj_tc_kernel<<<dim3(NPIX / 64, 2, BATCH), 256>>>(x, q_w, q_b, v_w, v_b);
    qnorm_kernel<<<BATCH, 256>>>();
    attn_tc_kernel<<<dim3(NPIX / QTILE, BATCH), 512, ATTN_SMEM>>>(x, gamma, out);
}